// round 1
// baseline (speedup 1.0000x reference)
#include <cuda_runtime.h>
#include <math.h>

#define BB 32
#define NN 512
#define TT 64
#define EE 128
#define OO 64
#define NITER 5
#define BNE (BB*NN*EE)      // 2,097,152
#define BN  (BB*NN)         // 16,384
#define L2E 1.442695040888963f

// ---------------- scratch (device globals; no allocation allowed) ----------------
__device__ float    g_lit[2][BNE];
__device__ float    g_emb[4][BNE];
__device__ float    g_tmp[4][BNE];
__device__ float    g_hid[4][BNE];
__device__ float    g_ah1[4][BN];
__device__ float    g_ah2[4][BN];
__device__ float    g_m2[4][BN];
__device__ float    g_iZ[4][BN];
__device__ unsigned g_mask[4][BN*(NN/32)];
__device__ float    g_xz[2][BB*TT*3*EE];
__device__ float    g_hfin[2][BB*EE];
__device__ float    g_rkT[2][3*EE*EE];
__device__ float    g_mid[2][BB*3*EE];
__device__ float    g_gemb[2][BB*OO];

// ---------------- generic SGEMM: C[M,Nn] = A[M,K] @ B[K,Nn], z-batched ----------------
// EPI: 0 none, 1 relu, 2 tanh(extra + acc) w/ extra indexed by (bz>>1)*sE, 3 +bias[col]
template<int EPI>
__global__ void __launch_bounds__(256) sgemm(
    const float* __restrict__ A, const float* __restrict__ Bm, float* __restrict__ C,
    int M, int Nn, int K,
    long long sA, long long sB, long long sC,
    const float* __restrict__ extra, long long sE)
{
    constexpr int BM = 128, BNt = 128, BK = 8, TM = 8, TN = 8;
    __shared__ float As[BK][BM];
    __shared__ float Bs[BK][BNt];
    const int bz = blockIdx.z;
    A  += (long long)bz * sA;
    Bm += (long long)bz * sB;
    C  += (long long)bz * sC;
    const int rowBase = blockIdx.x * BM;
    const int colBase = blockIdx.y * BNt;
    const int tid = threadIdx.x;
    const int tx = tid & 15, ty = tid >> 4;
    const int aRow = tid >> 1, aCol = (tid & 1) * 4;
    const int bRow = tid >> 5, bCol = (tid & 31) * 4;

    float acc[TM][TN];
#pragma unroll
    for (int i = 0; i < TM; i++)
#pragma unroll
        for (int j = 0; j < TN; j++) acc[i][j] = 0.f;

    const float* Aptr = A + (long long)(rowBase + aRow) * K + aCol;
    const float* Bptr = Bm + (long long)bRow * Nn + colBase + bCol;

    for (int k0 = 0; k0 < K; k0 += BK) {
        float4 av = *(const float4*)(Aptr + k0);
        float4 bv = *(const float4*)(Bptr + (long long)k0 * Nn);
        As[aCol + 0][aRow] = av.x;
        As[aCol + 1][aRow] = av.y;
        As[aCol + 2][aRow] = av.z;
        As[aCol + 3][aRow] = av.w;
        *(float4*)&Bs[bRow][bCol] = bv;
        __syncthreads();
#pragma unroll
        for (int k = 0; k < BK; k++) {
            float ra[TM], rb[TN];
            *(float4*)&ra[0] = *(const float4*)&As[k][ty * TM];
            *(float4*)&ra[4] = *(const float4*)&As[k][ty * TM + 4];
            *(float4*)&rb[0] = *(const float4*)&Bs[k][tx * TN];
            *(float4*)&rb[4] = *(const float4*)&Bs[k][tx * TN + 4];
#pragma unroll
            for (int i = 0; i < TM; i++)
#pragma unroll
                for (int j = 0; j < TN; j++)
                    acc[i][j] = fmaf(ra[i], rb[j], acc[i][j]);
        }
        __syncthreads();
    }

    const float* Ex = extra;
    if (EPI == 2) Ex = extra + (long long)(bz >> 1) * sE;
#pragma unroll
    for (int i = 0; i < TM; i++) {
        int row = rowBase + ty * TM + i;
        float* crow = C + (long long)row * Nn + colBase + tx * TN;
#pragma unroll
        for (int j0 = 0; j0 < TN; j0 += 4) {
            float vv[4];
#pragma unroll
            for (int q = 0; q < 4; q++) {
                float x = acc[i][j0 + q];
                if (EPI == 1) x = fmaxf(x, 0.f);
                else if (EPI == 2) x = tanhf(Ex[(long long)row * Nn + colBase + tx * TN + j0 + q] + x);
                else if (EPI == 3) x = x + extra[colBase + tx * TN + j0 + q];
                vv[q] = x;
            }
            float4 v; v.x = vv[0]; v.y = vv[1]; v.z = vv[2]; v.w = vv[3];
            *(float4*)(crow + j0) = v;
        }
    }
}

// ---------------- fused attention GEMM: out = softmax_masked(scores) @ emb ----------------
// grid: x = NN/128 row tiles, z = 4*BB (combo, batch). A tile generated on the fly.
__global__ void __launch_bounds__(256) att_gemm()
{
    constexpr int BM = 128, BK = 8, TM = 8, TN = 8;
    __shared__ float s_ah1[BM], s_m2[BM], s_iZ[BM];
    __shared__ float s_ah2[NN];
    __shared__ unsigned s_mask[BM][16];
    __shared__ float As[BK][BM];
    __shared__ float Bs[BK][EE];

    const int z = blockIdx.z;
    const int c = z >> 5, b = z & 31;
    const int rowBase = blockIdx.x * BM;
    const int tid = threadIdx.x;
    const float* emb = g_emb[c] + (long long)b * NN * EE;
    float* out = g_tmp[c] + (long long)b * NN * EE;
    const int rowOff = b * NN + rowBase;

    if (tid < BM) {
        s_ah1[tid] = g_ah1[c][rowOff + tid];
        s_m2[tid]  = g_m2[c][rowOff + tid];
        s_iZ[tid]  = g_iZ[c][rowOff + tid];
    }
    s_ah2[tid]       = g_ah2[c][b * NN + tid];
    s_ah2[tid + 256] = g_ah2[c][b * NN + tid + 256];
#pragma unroll
    for (int q = 0; q < 8; q++) {
        int idx = tid * 8 + q;
        int r = idx >> 4, w = idx & 15;
        s_mask[r][w] = g_mask[c][(long long)(rowOff + r) * 16 + w];
    }
    __syncthreads();

    const int tx = tid & 15, ty = tid >> 4;
    const int gi = tid >> 1, kk0 = (tid & 1) * 4;
    const int bRow = tid >> 5, bCol = (tid & 31) * 4;

    float acc[TM][TN];
#pragma unroll
    for (int i = 0; i < TM; i++)
#pragma unroll
        for (int j = 0; j < TN; j++) acc[i][j] = 0.f;

    const float a1v = s_ah1[gi], m2v = s_m2[gi], izv = s_iZ[gi];

    for (int kt = 0; kt < NN / BK; kt++) {
        const int j0 = kt * BK;
#pragma unroll
        for (int q = 0; q < 4; q++) {
            int k = kk0 + q, j = j0 + k;
            float s = a1v + s_ah2[j];
            s = s > 0.f ? s : 0.2f * s;
            unsigned bit = (s_mask[gi][j >> 5] >> (j & 31)) & 1u;
            As[k][gi] = bit ? exp2f(fmaf(s, L2E, -m2v)) * izv : 0.f;
        }
        float4 bv = *(const float4*)(emb + (long long)(j0 + bRow) * EE + bCol);
        *(float4*)&Bs[bRow][bCol] = bv;
        __syncthreads();
#pragma unroll
        for (int k = 0; k < BK; k++) {
            float ra[TM], rb[TN];
            *(float4*)&ra[0] = *(const float4*)&As[k][ty * TM];
            *(float4*)&ra[4] = *(const float4*)&As[k][ty * TM + 4];
            *(float4*)&rb[0] = *(const float4*)&Bs[k][tx * TN];
            *(float4*)&rb[4] = *(const float4*)&Bs[k][tx * TN + 4];
#pragma unroll
            for (int i = 0; i < TM; i++)
#pragma unroll
                for (int j = 0; j < TN; j++)
                    acc[i][j] = fmaf(ra[i], rb[j], acc[i][j]);
        }
        __syncthreads();
    }

#pragma unroll
    for (int i = 0; i < TM; i++) {
        int row = rowBase + ty * TM + i;
        float* crow = out + (long long)row * EE + tx * TN;
#pragma unroll
        for (int j0 = 0; j0 < TN; j0 += 4) {
            float4 v;
            v.x = acc[i][j0 + 0]; v.y = acc[i][j0 + 1];
            v.z = acc[i][j0 + 2]; v.w = acc[i][j0 + 3];
            *(float4*)(crow + j0) = v;
        }
    }
}

// ---------------- attention row scores: ah1/ah2 dots ----------------
__global__ void __launch_bounds__(256) scores_k(
    const float* __restrict__ cw1, const float* __restrict__ cb1,
    const float* __restrict__ cw2, const float* __restrict__ cb2,
    const float* __restrict__ lw1, const float* __restrict__ lb1,
    const float* __restrict__ lw2, const float* __restrict__ lb2)
{
    const int warp = threadIdx.x >> 5, lane = threadIdx.x & 31;
    const long long gid = (long long)blockIdx.x * 8 + warp;   // < 4*BN
    const int c = (int)(gid >> 14);
    const int rem = (int)(gid & 16383);
    const float* w1 = (c & 1) ? lw1 : cw1;
    const float* w2 = (c & 1) ? lw2 : cw2;
    const float* emb = g_emb[c] + (long long)rem * EE;
    float4 e = ((const float4*)emb)[lane];
    float4 a = ((const float4*)w1)[lane];
    float4 w = ((const float4*)w2)[lane];
    float d1 = e.x * a.x + e.y * a.y + e.z * a.z + e.w * a.w;
    float d2 = e.x * w.x + e.y * w.y + e.z * w.z + e.w * w.w;
#pragma unroll
    for (int o = 16; o; o >>= 1) {
        d1 += __shfl_xor_sync(0xffffffffu, d1, o);
        d2 += __shfl_xor_sync(0xffffffffu, d2, o);
    }
    if (lane == 0) {
        g_ah1[c][rem] = d1 + ((c & 1) ? lb1 : cb1)[0];
        g_ah2[c][rem] = d2 + ((c & 1) ? lb2 : cb2)[0];
    }
}

// ---------------- per-row softmax stats (max, 1/Z) over masked scores ----------------
__global__ void __launch_bounds__(256) stats_k()
{
    const int warp = threadIdx.x >> 5, lane = threadIdx.x & 31;
    const long long gid = (long long)blockIdx.x * 8 + warp;
    const int c = (int)(gid >> 14);
    const int rem = (int)(gid & 16383);
    const int b = rem >> 9;
    const float a1 = g_ah1[c][rem];
    const float* ah2 = g_ah2[c] + b * NN;
    const unsigned* mrow = g_mask[c] + (long long)rem * 16;
    float v[16];
    float mx = -1e30f;
#pragma unroll
    for (int q = 0; q < 16; q++) {
        int j = q * 32 + lane;
        float s = a1 + ah2[j];
        s = s > 0.f ? s : 0.2f * s;
        unsigned bit = (mrow[q] >> lane) & 1u;
        v[q] = bit ? s : -1e30f;
        mx = fmaxf(mx, v[q]);
    }
#pragma unroll
    for (int o = 16; o; o >>= 1) mx = fmaxf(mx, __shfl_xor_sync(0xffffffffu, mx, o));
    const float m2 = mx * L2E;
    float sum = 0.f;
#pragma unroll
    for (int q = 0; q < 16; q++)
        if (v[q] > -1e29f) sum += exp2f(fmaf(v[q], L2E, -m2));
#pragma unroll
    for (int o = 16; o; o >>= 1) sum += __shfl_xor_sync(0xffffffffu, sum, o);
    if (lane == 0) {
        if (sum > 0.f) { g_m2[c][rem] = m2; g_iZ[c][rem] = 1.f / sum; }
        else           { g_m2[c][rem] = 0.f; g_iZ[c][rem] = 0.f; }
    }
}

// ---------------- G -> bitmask (one warp per 32-bit word) ----------------
__global__ void __launch_bounds__(256) mask_k(
    const int* __restrict__ g0, const int* __restrict__ g1,
    const int* __restrict__ g2, const int* __restrict__ g3)
{
    const long long gid = ((long long)blockIdx.x * 256 + threadIdx.x) >> 5; // word id < 4*BN*16
    const int lane = threadIdx.x & 31;
    const int c = (int)(gid >> 18);
    const long long r = gid & 262143;
    const long long rowrem = r >> 4;
    const int w = (int)(r & 15);
    const int* G = (c == 0) ? g0 : (c == 1) ? g1 : (c == 2) ? g2 : g3;
    int val = G[rowrem * NN + w * 32 + lane];
    unsigned m = __ballot_sync(0xffffffffu, val != 0);
    if (lane == 0) g_mask[c][rowrem * 16 + w] = m;
}

// ---------------- emb init: relu(lit) replicated to 4 combos ----------------
__global__ void __launch_bounds__(1024) init_emb_k()
{
    const long long idx = (long long)blockIdx.x * 1024 + threadIdx.x; // < 4*BNE
    const int c = (int)(idx / BNE);
    const long long off = idx % BNE;
    g_emb[c][off] = fmaxf(g_lit[c >> 1][off], 0.f);
}

// ---------------- rk transpose ----------------
__global__ void __launch_bounds__(256) transpose_rk_k(
    const float* __restrict__ rk1, const float* __restrict__ rk2)
{
    const int idx = blockIdx.x * 256 + threadIdx.x;   // < 2*384*128
    const int s = idx / (3 * EE * EE);
    const int r = idx % (3 * EE * EE);
    const int j = r / EE, k = r % EE;
    const float* rk = s ? rk2 : rk1;
    g_rkT[s][r] = rk[k * 3 * EE + j];
}

// ---------------- GRU (reset_after): one block per (side,batch) ----------------
__global__ void __launch_bounds__(384) gru_k(const float* __restrict__ b1,
                                             const float* __restrict__ b2)
{
    const int s = blockIdx.x >> 5, b = blockIdx.x & 31;
    const float* xz = g_xz[s] + (long long)b * TT * 3 * EE;
    const float4* w4 = (const float4*)(g_rkT[s] + (long long)threadIdx.x * EE);
    const float* br = (s ? b2 : b1) + 3 * EE;
    __shared__ __align__(16) float hs[EE];
    __shared__ float hzs[3 * EE];
    const int j = threadIdx.x;
    if (j < EE) hs[j] = 0.f;
    __syncthreads();
    const float brj = br[j];
    for (int t = 0; t < TT; t++) {
        const float4* h4 = (const float4*)hs;
        float a0 = 0.f, a1 = 0.f, a2 = 0.f, a3 = 0.f;
#pragma unroll
        for (int q = 0; q < 32; q += 4) {
            float4 w, h;
            w = w4[q + 0]; h = h4[q + 0];
            a0 = fmaf(w.x, h.x, a0); a0 = fmaf(w.y, h.y, a0); a0 = fmaf(w.z, h.z, a0); a0 = fmaf(w.w, h.w, a0);
            w = w4[q + 1]; h = h4[q + 1];
            a1 = fmaf(w.x, h.x, a1); a1 = fmaf(w.y, h.y, a1); a1 = fmaf(w.z, h.z, a1); a1 = fmaf(w.w, h.w, a1);
            w = w4[q + 2]; h = h4[q + 2];
            a2 = fmaf(w.x, h.x, a2); a2 = fmaf(w.y, h.y, a2); a2 = fmaf(w.z, h.z, a2); a2 = fmaf(w.w, h.w, a2);
            w = w4[q + 3]; h = h4[q + 3];
            a3 = fmaf(w.x, h.x, a3); a3 = fmaf(w.y, h.y, a3); a3 = fmaf(w.z, h.z, a3); a3 = fmaf(w.w, h.w, a3);
        }
        hzs[j] = (a0 + a1) + (a2 + a3) + brj;
        __syncthreads();
        float hn = 0.f;
        if (j < EE) {
            const float* xzt = xz + t * 3 * EE;
            float zz = 1.f / (1.f + __expf(-(xzt[j] + hzs[j])));
            float rr = 1.f / (1.f + __expf(-(xzt[EE + j] + hzs[EE + j])));
            float hh = tanhf(xzt[2 * EE + j] + rr * hzs[2 * EE + j]);
            hn = zz * hs[j] + (1.f - zz) * hh;
        }
        __syncthreads();
        if (j < EE) hs[j] = hn;
        __syncthreads();
    }
    if (j < EE) g_hfin[s][b * EE + j] = hs[j];
}

// ---------------- sum over nodes + sem slot fill ----------------
__global__ void __launch_bounds__(128) accum_k()
{
    const int id = blockIdx.x, e = threadIdx.x;
    if (id < 4 * BB) {
        const int c = id >> 5, b = id & 31;
        const float* p = g_emb[c] + (long long)b * NN * EE + e;
        float sacc = 0.f;
        for (int n = 0; n < NN; n++) sacc += p[(long long)n * EE];
        g_mid[c >> 1][b * 3 * EE + (c & 1) * EE + e] = sacc;
    } else {
        const int k = id - 4 * BB;
        const int s = k >> 5, b = k & 31;
        g_mid[s][b * 3 * EE + 2 * EE + e] = g_hfin[s][b * EE + e];
    }
}

// ---------------- graph embedding head: mid @ Wout + bout ----------------
__global__ void __launch_bounds__(64) outemb_k(const float* __restrict__ Wout,
                                               const float* __restrict__ bout)
{
    const int s = blockIdx.x >> 5, b = blockIdx.x & 31;
    __shared__ float ms[3 * EE];
    for (int k = threadIdx.x; k < 3 * EE; k += 64) ms[k] = g_mid[s][b * 3 * EE + k];
    __syncthreads();
    const int o = threadIdx.x;
    float acc = bout[o];
    for (int k = 0; k < 3 * EE; k++) acc = fmaf(ms[k], Wout[k * OO + o], acc);
    g_gemb[s][b * OO + o] = acc;
}

// ---------------- cosine head ----------------
__global__ void __launch_bounds__(64) final_k(float* __restrict__ out)
{
    const int b = blockIdx.x, t = threadIdx.x;
    float x = g_gemb[0][b * OO + t], y = g_gemb[1][b * OO + t];
    float d = x * y, nx = x * x, ny = y * y;
    __shared__ float sd[2], sx[2], sy[2];
#pragma unroll
    for (int o = 16; o; o >>= 1) {
        d  += __shfl_xor_sync(0xffffffffu, d, o);
        nx += __shfl_xor_sync(0xffffffffu, nx, o);
        ny += __shfl_xor_sync(0xffffffffu, ny, o);
    }
    if ((t & 31) == 0) { sd[t >> 5] = d; sx[t >> 5] = nx; sy[t >> 5] = ny; }
    __syncthreads();
    if (t == 0) {
        float D = sd[0] + sd[1], X = sx[0] + sx[1], Y = sy[0] + sy[1];
        float cosv = D * rsqrtf(fmaxf(X, 1e-12f)) * rsqrtf(fmaxf(Y, 1e-12f));
        out[b] = (cosv + 1.f) * 0.5f;
    }
}

// ---------------- launch ----------------
extern "C" void kernel_launch(void* const* d_in, const int* in_sizes, int n_in,
                              void* d_out, int out_size)
{
    const int*   CFG1 = (const int*)d_in[0];
    const int*   LFG1 = (const int*)d_in[1];
    const float* LIT1 = (const float*)d_in[2];
    const float* SEM1 = (const float*)d_in[3];
    const int*   CFG2 = (const int*)d_in[4];
    const int*   LFG2 = (const int*)d_in[5];
    const float* LIT2 = (const float*)d_in[6];
    const float* SEM2 = (const float*)d_in[7];
    const float* Wl1  = (const float*)d_in[8];
    const float* g1k  = (const float*)d_in[9];
    const float* g1rk = (const float*)d_in[10];
    const float* g1b  = (const float*)d_in[11];
    const float* Wl2  = (const float*)d_in[12];
    const float* g2k  = (const float*)d_in[13];
    const float* g2rk = (const float*)d_in[14];
    const float* g2b  = (const float*)d_in[15];
    const float* cw1  = (const float*)d_in[16];
    const float* cb1  = (const float*)d_in[17];
    const float* cw2  = (const float*)d_in[18];
    const float* cb2  = (const float*)d_in[19];
    const float* lw1  = (const float*)d_in[20];
    const float* lb1  = (const float*)d_in[21];
    const float* lw2  = (const float*)d_in[22];
    const float* lb2  = (const float*)d_in[23];
    const float* mlp1 = (const float*)d_in[24];
    const float* mlp2 = (const float*)d_in[25];
    const float* Wout = (const float*)d_in[26];
    const float* bout = (const float*)d_in[27];

    float *p_lit, *p_emb, *p_tmp, *p_hid, *p_xz;
    cudaGetSymbolAddress((void**)&p_lit, g_lit);
    cudaGetSymbolAddress((void**)&p_emb, g_emb);
    cudaGetSymbolAddress((void**)&p_tmp, g_tmp);
    cudaGetSymbolAddress((void**)&p_hid, g_hid);
    cudaGetSymbolAddress((void**)&p_xz, g_xz);

    // one-time per call: masks, literal projections, GRU inputs
    mask_k<<<131072, 256>>>(CFG1, LFG1, CFG2, LFG2);
    sgemm<0><<<dim3(BN / 128, 1, 1), 256>>>(LIT1, Wl1, p_lit,       BN, EE, EE, 0, 0, 0, nullptr, 0);
    sgemm<0><<<dim3(BN / 128, 1, 1), 256>>>(LIT2, Wl2, p_lit + BNE, BN, EE, EE, 0, 0, 0, nullptr, 0);
    init_emb_k<<<8192, 1024>>>();
    sgemm<3><<<dim3(BB * TT / 128, 3, 1), 256>>>(SEM1, g1k, p_xz,                    BB * TT, 3 * EE, EE, 0, 0, 0, g1b, 0);
    sgemm<3><<<dim3(BB * TT / 128, 3, 1), 256>>>(SEM2, g2k, p_xz + BB * TT * 3 * EE, BB * TT, 3 * EE, EE, 0, 0, 0, g2b, 0);
    transpose_rk_k<<<2 * 3 * EE * EE / 256, 256>>>(g1rk, g2rk);
    gru_k<<<64, 384>>>(g1b, g2b);

    // 5 lockstep iterations over all 4 (side,graph) combos
    for (int it = 0; it < NITER; it++) {
        scores_k<<<4 * BN / 8, 256>>>(cw1, cb1, cw2, cb2, lw1, lb1, lw2, lb2);
        stats_k<<<4 * BN / 8, 256>>>();
        att_gemm<<<dim3(NN / 128, 1, 4 * BB), 256>>>();
        sgemm<1><<<dim3(BN / 128, 1, 4), 256>>>(p_tmp, mlp1, p_hid, BN, EE, EE, BNE, 0, BNE, nullptr, 0);
        sgemm<2><<<dim3(BN / 128, 1, 4), 256>>>(p_hid, mlp2, p_emb, BN, EE, EE, BNE, 0, BNE, p_lit, BNE);
    }

    accum_k<<<6 * BB, 128>>>();
    outemb_k<<<2 * BB, 64>>>(Wout, bout);
    final_k<<<BB, 64>>>((float*)d_out);
}

// round 2
// speedup vs baseline: 2.2768x; 2.2768x over previous
#include <cuda_runtime.h>
#include <cuda_fp16.h>
#include <math.h>

#define BB 32
#define NN 512
#define TT 64
#define EE 128
#define OO 64
#define NITER 5
#define BNE (BB*NN*EE)      // 2,097,152
#define BN  (BB*NN)         // 16,384
#define L2E 1.442695040888963f

// ---------------- scratch (device globals; no allocation allowed) ----------------
__device__ float    g_lit[2][BNE];
__device__ float    g_emb[4][BNE];
__device__ float    g_ah1[4][BN];
__device__ float    g_ah2[4][BN];
__device__ float    g_iZ[4][BN];
__device__ unsigned g_mask[4][BN*(NN/32)];
__device__ float    g_xz[2][BB*TT*3*EE];
__device__ float    g_hfin[2][BB*EE];
__device__ float    g_rkT[2][3*EE*EE];
__device__ float    g_mid[2][BB*3*EE];
__device__ float    g_gemb[2][BB*OO];
// fp16 operands
__device__ __half   g_P[4ll*BN*NN];          // 64 MB unnormalized probs
__device__ __half   g_embh[4ll*BNE];
__device__ __half   g_tmph[4ll*BN*EE];
__device__ __half   g_hidh[4ll*BN*EE];
__device__ __half   g_w1h[EE*EE];
__device__ __half   g_w2h[EE*EE];

// ================= mma.sync helpers =================
__device__ __forceinline__ unsigned sptr(const void* p) {
    return (unsigned)__cvta_generic_to_shared(p);
}
__device__ __forceinline__ void cpasync16(unsigned s, const void* g) {
    asm volatile("cp.async.cg.shared.global [%0], [%1], 16;\n" :: "r"(s), "l"(g));
}
__device__ __forceinline__ void ldsm4(unsigned* r, unsigned addr) {
    asm volatile("ldmatrix.sync.aligned.m8n8.x4.shared.b16 {%0,%1,%2,%3},[%4];\n"
                 : "=r"(r[0]), "=r"(r[1]), "=r"(r[2]), "=r"(r[3]) : "r"(addr));
}
__device__ __forceinline__ void ldsm4t(unsigned* r, unsigned addr) {
    asm volatile("ldmatrix.sync.aligned.m8n8.x4.trans.shared.b16 {%0,%1,%2,%3},[%4];\n"
                 : "=r"(r[0]), "=r"(r[1]), "=r"(r[2]), "=r"(r[3]) : "r"(addr));
}
__device__ __forceinline__ void mma16816(float* d, const unsigned* a, unsigned b0, unsigned b1) {
    asm volatile(
        "mma.sync.aligned.m16n8k16.row.col.f32.f16.f16.f32 "
        "{%0,%1,%2,%3},{%4,%5,%6,%7},{%8,%9},{%0,%1,%2,%3};\n"
        : "+f"(d[0]), "+f"(d[1]), "+f"(d[2]), "+f"(d[3])
        : "r"(a[0]), "r"(a[1]), "r"(a[2]), "r"(a[3]), "r"(b0), "r"(b1));
}

// ================= fp16 tensor-core GEMM =================
// C[M,128] = A[M,KTOT](fp16) @ B[KTOT,128](fp16), z-batched. Block tile 128x128,
// 8 warps (2x4), warp tile 64x32, KC=32 double-buffered via cp.async.
// EPI 0: x *= iZ[z*sE + row]        -> fp16 outh
// EPI 1: relu(x)                    -> fp16 outh
// EPI 2: tanh(lit + x), lit = extra + (z>>1)*sE -> fp32 outf AND fp16 outh
#define KC 32
#define AS_STRIDE 40    // halves: 80B rows (80/16 odd -> conflict-free ldmatrix)
#define BS_STRIDE 136   // halves: 272B rows

template<int EPI, int KTOT>
__global__ void __launch_bounds__(256, 2) h16gemm(
    const __half* __restrict__ Ag, int lda, long long sA,
    const __half* __restrict__ Bg, long long sB,
    __half* __restrict__ outh, long long sO,
    float* __restrict__ outf,
    const float* __restrict__ extra, long long sE)
{
    __shared__ __align__(16) __half As[2][128 * AS_STRIDE];
    __shared__ __align__(16) __half Bs[2][KC * BS_STRIDE];

    const int z = blockIdx.z;
    const int rowBase = blockIdx.x * 128;
    const __half* Ap = Ag + (long long)z * sA + (long long)rowBase * lda;
    const __half* Bp = Bg + (long long)z * sB;
    const int tid = threadIdx.x;
    const int warp = tid >> 5, lane = tid & 31;
    const int wm = (warp >> 2) * 64, wn = (warp & 3) * 32;

    float acc[4][4][4];
#pragma unroll
    for (int mi = 0; mi < 4; mi++)
#pragma unroll
        for (int j = 0; j < 4; j++)
#pragma unroll
            for (int q = 0; q < 4; q++) acc[mi][j][q] = 0.f;

    // cp.async staging indices
    const int ar = tid >> 2, as_ = tid & 3;       // A: rows 0..63 (+64 second), 4x16B segs
    const int br = tid >> 4, bs_ = tid & 15;      // B: rows 0..15 (KC=32 -> 2 halves? no: 32 rows x 16 segs = 512 -> 2/thread)

    auto loadChunk = [&](int kc, int stg) {
#pragma unroll
        for (int i = 0; i < 2; i++) {
            int r = ar + i * 64;
            cpasync16(sptr(&As[stg][r * AS_STRIDE + as_ * 8]),
                      Ap + (long long)r * lda + kc + as_ * 8);
        }
#pragma unroll
        for (int i = 0; i < 2; i++) {
            int r = br + i * 16;
            cpasync16(sptr(&Bs[stg][r * BS_STRIDE + bs_ * 8]),
                      Bp + (long long)(kc + r) * 128 + bs_ * 8);
        }
        asm volatile("cp.async.commit_group;\n");
    };

    constexpr int NCH = KTOT / KC;
    loadChunk(0, 0);
    for (int ch = 0; ch < NCH; ch++) {
        if (ch + 1 < NCH) {
            loadChunk((ch + 1) * KC, (ch + 1) & 1);
            asm volatile("cp.async.wait_group 1;\n");
        } else {
            asm volatile("cp.async.wait_group 0;\n");
        }
        __syncthreads();
        const __half* as = As[ch & 1];
        const __half* bs = Bs[ch & 1];
#pragma unroll
        for (int ks = 0; ks < KC / 16; ks++) {
            unsigned a[4][4];
#pragma unroll
            for (int mi = 0; mi < 4; mi++)
                ldsm4(a[mi], sptr(as + (wm + mi * 16 + (lane & 15)) * AS_STRIDE
                                     + ks * 16 + (lane >> 4) * 8));
            unsigned b[2][4];
#pragma unroll
            for (int nb = 0; nb < 2; nb++)
                ldsm4t(b[nb], sptr(bs + (ks * 16 + (lane & 15)) * BS_STRIDE
                                      + wn + nb * 16 + (lane >> 4) * 8));
#pragma unroll
            for (int mi = 0; mi < 4; mi++)
#pragma unroll
                for (int j = 0; j < 4; j++)
                    mma16816(acc[mi][j], a[mi], b[j >> 1][(j & 1) * 2], b[j >> 1][(j & 1) * 2 + 1]);
        }
        __syncthreads();
    }

    // epilogue
#pragma unroll
    for (int mi = 0; mi < 4; mi++) {
#pragma unroll
        for (int h = 0; h < 2; h++) {
            const int r = wm + mi * 16 + (lane >> 2) + h * 8;
            const long long grow = rowBase + r;
            float rowscale = 1.f;
            if (EPI == 0) rowscale = extra[(long long)z * sE + grow];
#pragma unroll
            for (int j = 0; j < 4; j++) {
                const int c0 = wn + j * 8 + (lane & 3) * 2;
                float x0 = acc[mi][j][h * 2 + 0];
                float x1 = acc[mi][j][h * 2 + 1];
                if (EPI == 0) { x0 *= rowscale; x1 *= rowscale; }
                if (EPI == 1) { x0 = fmaxf(x0, 0.f); x1 = fmaxf(x1, 0.f); }
                if (EPI == 2) {
                    const float* lp = extra + ((long long)(z >> 1)) * sE + grow * 128 + c0;
                    float2 l = *(const float2*)lp;
                    x0 = tanhf(l.x + x0);
                    x1 = tanhf(l.y + x1);
                    *(float2*)(outf + (long long)z * sO + grow * 128 + c0) = make_float2(x0, x1);
                }
                *(__half2*)(outh + (long long)z * sO + grow * 128 + c0) = __floats2half2_rn(x0, x1);
            }
        }
    }
}

// ---------------- FFMA SGEMM for one-time setup GEMMs ----------------
// EPI: 0 none, 3 +bias[col]
template<int EPI>
__global__ void __launch_bounds__(256) sgemm(
    const float* __restrict__ A, const float* __restrict__ Bm, float* __restrict__ C,
    int M, int Nn, int K, const float* __restrict__ extra)
{
    constexpr int BM = 128, BNt = 128, BK = 8, TM = 8, TN = 8;
    __shared__ float As[BK][BM];
    __shared__ float Bs[BK][BNt];
    const int rowBase = blockIdx.x * BM;
    const int colBase = blockIdx.y * BNt;
    const int tid = threadIdx.x;
    const int tx = tid & 15, ty = tid >> 4;
    const int aRow = tid >> 1, aCol = (tid & 1) * 4;
    const int bRow = tid >> 5, bCol = (tid & 31) * 4;

    float acc[TM][TN];
#pragma unroll
    for (int i = 0; i < TM; i++)
#pragma unroll
        for (int j = 0; j < TN; j++) acc[i][j] = 0.f;

    const float* Aptr = A + (long long)(rowBase + aRow) * K + aCol;
    const float* Bptr = Bm + (long long)bRow * Nn + colBase + bCol;

    for (int k0 = 0; k0 < K; k0 += BK) {
        float4 av = *(const float4*)(Aptr + k0);
        float4 bv = *(const float4*)(Bptr + (long long)k0 * Nn);
        As[aCol + 0][aRow] = av.x;
        As[aCol + 1][aRow] = av.y;
        As[aCol + 2][aRow] = av.z;
        As[aCol + 3][aRow] = av.w;
        *(float4*)&Bs[bRow][bCol] = bv;
        __syncthreads();
#pragma unroll
        for (int k = 0; k < BK; k++) {
            float ra[TM], rb[TN];
            *(float4*)&ra[0] = *(const float4*)&As[k][ty * TM];
            *(float4*)&ra[4] = *(const float4*)&As[k][ty * TM + 4];
            *(float4*)&rb[0] = *(const float4*)&Bs[k][tx * TN];
            *(float4*)&rb[4] = *(const float4*)&Bs[k][tx * TN + 4];
#pragma unroll
            for (int i = 0; i < TM; i++)
#pragma unroll
                for (int j = 0; j < TN; j++)
                    acc[i][j] = fmaf(ra[i], rb[j], acc[i][j]);
        }
        __syncthreads();
    }
#pragma unroll
    for (int i = 0; i < TM; i++) {
        int row = rowBase + ty * TM + i;
        float* crow = C + (long long)row * Nn + colBase + tx * TN;
#pragma unroll
        for (int j0 = 0; j0 < TN; j0 += 4) {
            float4 v;
            float vv[4];
#pragma unroll
            for (int q = 0; q < 4; q++) {
                float x = acc[i][j0 + q];
                if (EPI == 3) x = x + extra[colBase + tx * TN + j0 + q];
                vv[q] = x;
            }
            v.x = vv[0]; v.y = vv[1]; v.z = vv[2]; v.w = vv[3];
            *(float4*)(crow + j0) = v;
        }
    }
}

// ---------------- attention row scores: ah1/ah2 dots ----------------
__global__ void __launch_bounds__(256) scores_k(
    const float* __restrict__ cw1, const float* __restrict__ cb1,
    const float* __restrict__ cw2, const float* __restrict__ cb2,
    const float* __restrict__ lw1, const float* __restrict__ lb1,
    const float* __restrict__ lw2, const float* __restrict__ lb2)
{
    const int warp = threadIdx.x >> 5, lane = threadIdx.x & 31;
    const long long gid = (long long)blockIdx.x * 8 + warp;   // < 4*BN
    const int c = (int)(gid >> 14);
    const int rem = (int)(gid & 16383);
    const float* w1 = (c & 1) ? lw1 : cw1;
    const float* w2 = (c & 1) ? lw2 : cw2;
    const float* emb = g_emb[c] + (long long)rem * EE;
    float4 e = ((const float4*)emb)[lane];
    float4 a = ((const float4*)w1)[lane];
    float4 w = ((const float4*)w2)[lane];
    float d1 = e.x * a.x + e.y * a.y + e.z * a.z + e.w * a.w;
    float d2 = e.x * w.x + e.y * w.y + e.z * w.z + e.w * w.w;
#pragma unroll
    for (int o = 16; o; o >>= 1) {
        d1 += __shfl_xor_sync(0xffffffffu, d1, o);
        d2 += __shfl_xor_sync(0xffffffffu, d2, o);
    }
    if (lane == 0) {
        g_ah1[c][rem] = d1 + ((c & 1) ? lb1 : cb1)[0];
        g_ah2[c][rem] = d2 + ((c & 1) ? lb2 : cb2)[0];
    }
}

// ---------------- probs: row max + sum + unnormalized fp16 P ----------------
__global__ void __launch_bounds__(256) probs_k()
{
    const int warp = threadIdx.x >> 5, lane = threadIdx.x & 31;
    const long long gid = (long long)blockIdx.x * 8 + warp;   // row id < 4*BN
    const int c = (int)(gid >> 14);
    const int rem = (int)(gid & 16383);
    const int b = rem >> 9;
    const float a1 = g_ah1[c][rem];
    const float4* ah2 = (const float4*)(g_ah2[c] + b * NN);
    unsigned mword = g_mask[c][(long long)rem * 16 + (lane >> 1)];
    unsigned mbits = mword >> ((lane & 1) * 16);

    float s[16];
    float mx = -1e30f;
#pragma unroll
    for (int q4 = 0; q4 < 4; q4++) {
        float4 v = ah2[lane * 4 + q4];
        float vv[4] = {v.x, v.y, v.z, v.w};
#pragma unroll
        for (int t = 0; t < 4; t++) {
            int q = q4 * 4 + t;
            float sc = a1 + vv[t];
            sc = sc > 0.f ? sc : 0.2f * sc;
            s[q] = sc;
            float ms = ((mbits >> q) & 1u) ? sc : -1e30f;
            mx = fmaxf(mx, ms);
        }
    }
#pragma unroll
    for (int o = 16; o; o >>= 1) mx = fmaxf(mx, __shfl_xor_sync(0xffffffffu, mx, o));
    const float m2 = mx * L2E;
    float sum = 0.f;
    __half2 hh[8];
#pragma unroll
    for (int i = 0; i < 8; i++) {
        float p0 = ((mbits >> (2 * i)) & 1u) ? exp2f(fmaf(s[2 * i], L2E, -m2)) : 0.f;
        float p1 = ((mbits >> (2 * i + 1)) & 1u) ? exp2f(fmaf(s[2 * i + 1], L2E, -m2)) : 0.f;
        sum += p0 + p1;
        hh[i] = __floats2half2_rn(p0, p1);
    }
#pragma unroll
    for (int o = 16; o; o >>= 1) sum += __shfl_xor_sync(0xffffffffu, sum, o);

    uint4* dst = (uint4*)(g_P + ((long long)c * BN + rem) * NN + lane * 16);
    dst[0] = *(uint4*)&hh[0];
    dst[1] = *(uint4*)&hh[4];
    if (lane == 0) g_iZ[c][rem] = (sum > 0.f) ? 1.f / sum : 0.f;
}

// ---------------- G -> bitmask ----------------
__global__ void __launch_bounds__(256) mask_k(
    const int* __restrict__ g0, const int* __restrict__ g1,
    const int* __restrict__ g2, const int* __restrict__ g3)
{
    const long long gid = ((long long)blockIdx.x * 256 + threadIdx.x) >> 5;
    const int lane = threadIdx.x & 31;
    const int c = (int)(gid >> 18);
    const long long r = gid & 262143;
    const long long rowrem = r >> 4;
    const int w = (int)(r & 15);
    const int* G = (c == 0) ? g0 : (c == 1) ? g1 : (c == 2) ? g2 : g3;
    int val = G[rowrem * NN + w * 32 + lane];
    unsigned m = __ballot_sync(0xffffffffu, val != 0);
    if (lane == 0) g_mask[c][rowrem * 16 + w] = m;
}

// ---------------- emb init: relu(lit) -> fp32 + fp16 ----------------
__global__ void __launch_bounds__(1024) init_emb_k()
{
    const long long idx = (long long)blockIdx.x * 1024 + threadIdx.x; // < 4*BNE
    const int c = (int)(idx / BNE);
    const long long off = idx % BNE;
    float v = fmaxf(g_lit[c >> 1][off], 0.f);
    g_emb[c][off] = v;
    g_embh[idx] = __float2half_rn(v);
}

// ---------------- mlp weights -> fp16 ----------------
__global__ void __launch_bounds__(256) w16_k(const float* __restrict__ m1,
                                             const float* __restrict__ m2)
{
    int i = blockIdx.x * 256 + threadIdx.x; // < 2*16384
    if (i < EE * EE) g_w1h[i] = __float2half_rn(m1[i]);
    else g_w2h[i - EE * EE] = __float2half_rn(m2[i - EE * EE]);
}

// ---------------- rk transpose ----------------
__global__ void __launch_bounds__(256) transpose_rk_k(
    const float* __restrict__ rk1, const float* __restrict__ rk2)
{
    const int idx = blockIdx.x * 256 + threadIdx.x;   // < 2*384*128
    const int s = idx / (3 * EE * EE);
    const int r = idx % (3 * EE * EE);
    const int j = r / EE, k = r % EE;
    const float* rk = s ? rk2 : rk1;
    g_rkT[s][r] = rk[k * 3 * EE + j];
}

// ---------------- GRU (reset_after): one block per (side,batch) ----------------
__global__ void __launch_bounds__(384) gru_k(const float* __restrict__ b1,
                                             const float* __restrict__ b2)
{
    const int s = blockIdx.x >> 5, b = blockIdx.x & 31;
    const float* xz = g_xz[s] + (long long)b * TT * 3 * EE;
    const float4* w4 = (const float4*)(g_rkT[s] + (long long)threadIdx.x * EE);
    const float* br = (s ? b2 : b1) + 3 * EE;
    __shared__ __align__(16) float hs[EE];
    __shared__ float hzs[3 * EE];
    const int j = threadIdx.x;
    if (j < EE) hs[j] = 0.f;
    __syncthreads();
    const float brj = br[j];
    for (int t = 0; t < TT; t++) {
        const float4* h4 = (const float4*)hs;
        float a0 = 0.f, a1 = 0.f, a2 = 0.f, a3 = 0.f;
#pragma unroll
        for (int q = 0; q < 32; q += 4) {
            float4 w, h;
            w = w4[q + 0]; h = h4[q + 0];
            a0 = fmaf(w.x, h.x, a0); a0 = fmaf(w.y, h.y, a0); a0 = fmaf(w.z, h.z, a0); a0 = fmaf(w.w, h.w, a0);
            w = w4[q + 1]; h = h4[q + 1];
            a1 = fmaf(w.x, h.x, a1); a1 = fmaf(w.y, h.y, a1); a1 = fmaf(w.z, h.z, a1); a1 = fmaf(w.w, h.w, a1);
            w = w4[q + 2]; h = h4[q + 2];
            a2 = fmaf(w.x, h.x, a2); a2 = fmaf(w.y, h.y, a2); a2 = fmaf(w.z, h.z, a2); a2 = fmaf(w.w, h.w, a2);
            w = w4[q + 3]; h = h4[q + 3];
            a3 = fmaf(w.x, h.x, a3); a3 = fmaf(w.y, h.y, a3); a3 = fmaf(w.z, h.z, a3); a3 = fmaf(w.w, h.w, a3);
        }
        hzs[j] = (a0 + a1) + (a2 + a3) + brj;
        __syncthreads();
        float hn = 0.f;
        if (j < EE) {
            const float* xzt = xz + t * 3 * EE;
            float zz = 1.f / (1.f + __expf(-(xzt[j] + hzs[j])));
            float rr = 1.f / (1.f + __expf(-(xzt[EE + j] + hzs[EE + j])));
            float hh = tanhf(xzt[2 * EE + j] + rr * hzs[2 * EE + j]);
            hn = zz * hs[j] + (1.f - zz) * hh;
        }
        __syncthreads();
        if (j < EE) hs[j] = hn;
        __syncthreads();
    }
    if (j < EE) g_hfin[s][b * EE + j] = hs[j];
}

// ---------------- sum over nodes + sem slot fill ----------------
__global__ void __launch_bounds__(128) accum_k()
{
    const int id = blockIdx.x, e = threadIdx.x;
    if (id < 4 * BB) {
        const int c = id >> 5, b = id & 31;
        const float* p = g_emb[c] + (long long)b * NN * EE + e;
        float sacc = 0.f;
        for (int n = 0; n < NN; n++) sacc += p[(long long)n * EE];
        g_mid[c >> 1][b * 3 * EE + (c & 1) * EE + e] = sacc;
    } else {
        const int k = id - 4 * BB;
        const int s = k >> 5, b = k & 31;
        g_mid[s][b * 3 * EE + 2 * EE + e] = g_hfin[s][b * EE + e];
    }
}

// ---------------- graph embedding head ----------------
__global__ void __launch_bounds__(64) outemb_k(const float* __restrict__ Wout,
                                               const float* __restrict__ bout)
{
    const int s = blockIdx.x >> 5, b = blockIdx.x & 31;
    __shared__ float ms[3 * EE];
    for (int k = threadIdx.x; k < 3 * EE; k += 64) ms[k] = g_mid[s][b * 3 * EE + k];
    __syncthreads();
    const int o = threadIdx.x;
    float acc = bout[o];
    for (int k = 0; k < 3 * EE; k++) acc = fmaf(ms[k], Wout[k * OO + o], acc);
    g_gemb[s][b * OO + o] = acc;
}

// ---------------- cosine head ----------------
__global__ void __launch_bounds__(64) final_k(float* __restrict__ out)
{
    const int b = blockIdx.x, t = threadIdx.x;
    float x = g_gemb[0][b * OO + t], y = g_gemb[1][b * OO + t];
    float d = x * y, nx = x * x, ny = y * y;
    __shared__ float sd[2], sx[2], sy[2];
#pragma unroll
    for (int o = 16; o; o >>= 1) {
        d  += __shfl_xor_sync(0xffffffffu, d, o);
        nx += __shfl_xor_sync(0xffffffffu, nx, o);
        ny += __shfl_xor_sync(0xffffffffu, ny, o);
    }
    if ((t & 31) == 0) { sd[t >> 5] = d; sx[t >> 5] = nx; sy[t >> 5] = ny; }
    __syncthreads();
    if (t == 0) {
        float D = sd[0] + sd[1], X = sx[0] + sx[1], Y = sy[0] + sy[1];
        float cosv = D * rsqrtf(fmaxf(X, 1e-12f)) * rsqrtf(fmaxf(Y, 1e-12f));
        out[b] = (cosv + 1.f) * 0.5f;
    }
}

// ---------------- launch ----------------
extern "C" void kernel_launch(void* const* d_in, const int* in_sizes, int n_in,
                              void* d_out, int out_size)
{
    const int*   CFG1 = (const int*)d_in[0];
    const int*   LFG1 = (const int*)d_in[1];
    const float* LIT1 = (const float*)d_in[2];
    const float* SEM1 = (const float*)d_in[3];
    const int*   CFG2 = (const int*)d_in[4];
    const int*   LFG2 = (const int*)d_in[5];
    const float* LIT2 = (const float*)d_in[6];
    const float* SEM2 = (const float*)d_in[7];
    const float* Wl1  = (const float*)d_in[8];
    const float* g1k  = (const float*)d_in[9];
    const float* g1rk = (const float*)d_in[10];
    const float* g1b  = (const float*)d_in[11];
    const float* Wl2  = (const float*)d_in[12];
    const float* g2k  = (const float*)d_in[13];
    const float* g2rk = (const float*)d_in[14];
    const float* g2b  = (const float*)d_in[15];
    const float* cw1  = (const float*)d_in[16];
    const float* cb1  = (const float*)d_in[17];
    const float* cw2  = (const float*)d_in[18];
    const float* cb2  = (const float*)d_in[19];
    const float* lw1  = (const float*)d_in[20];
    const float* lb1  = (const float*)d_in[21];
    const float* lw2  = (const float*)d_in[22];
    const float* lb2  = (const float*)d_in[23];
    const float* mlp1 = (const float*)d_in[24];
    const float* mlp2 = (const float*)d_in[25];
    const float* Wout = (const float*)d_in[26];
    const float* bout = (const float*)d_in[27];

    float *p_lit, *p_emb, *p_xz, *p_iZ;
    __half *p_P, *p_embh, *p_tmph, *p_hidh, *p_w1h, *p_w2h;
    cudaGetSymbolAddress((void**)&p_lit, g_lit);
    cudaGetSymbolAddress((void**)&p_emb, g_emb);
    cudaGetSymbolAddress((void**)&p_xz, g_xz);
    cudaGetSymbolAddress((void**)&p_iZ, g_iZ);
    cudaGetSymbolAddress((void**)&p_P, g_P);
    cudaGetSymbolAddress((void**)&p_embh, g_embh);
    cudaGetSymbolAddress((void**)&p_tmph, g_tmph);
    cudaGetSymbolAddress((void**)&p_hidh, g_hidh);
    cudaGetSymbolAddress((void**)&p_w1h, g_w1h);
    cudaGetSymbolAddress((void**)&p_w2h, g_w2h);

    // one-time: masks, literal projections, GRU inputs, weight conversion
    mask_k<<<131072, 256>>>(CFG1, LFG1, CFG2, LFG2);
    sgemm<0><<<dim3(BN / 128, 1, 1), 256>>>(LIT1, Wl1, p_lit,       BN, EE, EE, nullptr);
    sgemm<0><<<dim3(BN / 128, 1, 1), 256>>>(LIT2, Wl2, p_lit + BNE, BN, EE, EE, nullptr);
    init_emb_k<<<8192, 1024>>>();
    sgemm<3><<<dim3(BB * TT / 128, 3, 1), 256>>>(SEM1, g1k, p_xz,                    BB * TT, 3 * EE, EE, g1b);
    sgemm<3><<<dim3(BB * TT / 128, 3, 1), 256>>>(SEM2, g2k, p_xz + BB * TT * 3 * EE, BB * TT, 3 * EE, EE, g2b);
    transpose_rk_k<<<2 * 3 * EE * EE / 256, 256>>>(g1rk, g2rk);
    gru_k<<<64, 384>>>(g1b, g2b);
    w16_k<<<2 * EE * EE / 256, 256>>>(mlp1, mlp2);

    // 5 lockstep iterations over all 4 (side,graph) combos
    for (int it = 0; it < NITER; it++) {
        scores_k<<<4 * BN / 8, 256>>>(cw1, cb1, cw2, cb2, lw1, lb1, lw2, lb2);
        probs_k<<<4 * BN / 8, 256>>>();
        // att: tmph = fp16( iZ * (P @ embh) )
        h16gemm<0, NN><<<dim3(NN / 128, 1, 4 * BB), 256>>>(
            p_P, NN, (long long)NN * NN, p_embh, (long long)NN * EE,
            p_tmph, (long long)NN * EE, nullptr, p_iZ, NN);
        // mlp1: hidh = fp16(relu(tmph @ W1))
        h16gemm<1, EE><<<dim3(BN / 128, 1, 4), 256>>>(
            p_tmph, EE, (long long)BN * EE, p_w1h, 0,
            p_hidh, (long long)BN * EE, nullptr, nullptr, 0);
        // mlp2: emb = tanh(lit + hidh @ W2) -> fp32 + fp16
        h16gemm<2, EE><<<dim3(BN / 128, 1, 4), 256>>>(
            p_hidh, EE, (long long)BN * EE, p_w2h, 0,
            p_embh, (long long)BN * EE, p_emb, p_lit, (long long)BNE);
    }

    accum_k<<<6 * BB, 128>>>();
    outemb_k<<<2 * BB, 64>>>(Wout, bout);
    final_k<<<BB, 64>>>((float*)d_out);
}

// round 3
// speedup vs baseline: 2.6904x; 1.1817x over previous
#include <cuda_runtime.h>
#include <cuda_fp16.h>
#include <math.h>

#define BB 32
#define NN 512
#define TT 64
#define EE 128
#define OO 64
#define NITER 5
#define BNE (BB*NN*EE)      // 2,097,152
#define BN  (BB*NN)         // 16,384
#define L2E 1.442695040888963f

// ---------------- scratch (device globals; no allocation allowed) ----------------
__device__ float    g_lit[2][BNE];
__device__ float    g_emb[4][BNE];     // fp32 init emb (scores_k only)
__device__ float    g_ah1[4][BN];
__device__ float    g_ah2[4][BN];
__device__ unsigned g_mask[4][BN*(NN/32)];
__device__ float    g_xz[2][BB*TT*3*EE];
__device__ float    g_hfin[2][BB*EE];
__device__ float    g_rkT[2][3*EE*EE];
__device__ float    g_mid[2][BB*3*EE];
__device__ float    g_gemb[2][BB*OO];
__device__ __half   g_embh[4ll*BNE];
__device__ __half   g_w1h[EE*EE];
__device__ __half   g_w2h[EE*EE];

// ================= helpers =================
__device__ __forceinline__ unsigned sptr(const void* p) {
    return (unsigned)__cvta_generic_to_shared(p);
}
__device__ __forceinline__ void cpasync16(unsigned s, const void* g) {
    asm volatile("cp.async.cg.shared.global [%0], [%1], 16;\n" :: "r"(s), "l"(g));
}
__device__ __forceinline__ void ldsm4(unsigned* r, unsigned addr) {
    asm volatile("ldmatrix.sync.aligned.m8n8.x4.shared.b16 {%0,%1,%2,%3},[%4];\n"
                 : "=r"(r[0]), "=r"(r[1]), "=r"(r[2]), "=r"(r[3]) : "r"(addr));
}
__device__ __forceinline__ void ldsm4t(unsigned* r, unsigned addr) {
    asm volatile("ldmatrix.sync.aligned.m8n8.x4.trans.shared.b16 {%0,%1,%2,%3},[%4];\n"
                 : "=r"(r[0]), "=r"(r[1]), "=r"(r[2]), "=r"(r[3]) : "r"(addr));
}
__device__ __forceinline__ void mma16816(float* d, const unsigned* a, unsigned b0, unsigned b1) {
    asm volatile(
        "mma.sync.aligned.m16n8k16.row.col.f32.f16.f16.f32 "
        "{%0,%1,%2,%3},{%4,%5,%6,%7},{%8,%9},{%0,%1,%2,%3};\n"
        : "+f"(d[0]), "+f"(d[1]), "+f"(d[2]), "+f"(d[3])
        : "r"(a[0]), "r"(a[1]), "r"(a[2]), "r"(a[3]), "r"(b0), "r"(b1));
}
__device__ __forceinline__ float ex2a(float x) {
    float y; asm("ex2.approx.f32 %0,%1;\n" : "=f"(y) : "f"(x)); return y;
}

// one k=16 mma step: A smem (stride astr halves, col offset aoff), B smem chunk (stride 136, row offset ks*16)
__device__ __forceinline__ void mma_ks(const __half* as_, int astr, int aoff,
                                       const __half* bs_, int ks,
                                       int wm, int wn, int lane, float acc[4][4][4])
{
    unsigned a[4][4], bfr[2][4];
#pragma unroll
    for (int mi = 0; mi < 4; mi++)
        ldsm4(a[mi], sptr(as_ + (wm + mi * 16 + (lane & 15)) * astr + aoff + (lane >> 4) * 8));
#pragma unroll
    for (int nb = 0; nb < 2; nb++)
        ldsm4t(bfr[nb], sptr(bs_ + (ks * 16 + (lane & 15)) * 136 + wn + nb * 16 + (lane >> 4) * 8));
#pragma unroll
    for (int mi = 0; mi < 4; mi++)
#pragma unroll
        for (int j = 0; j < 4; j++)
            mma16816(acc[mi][j], a[mi], bfr[j >> 1][(j & 1) * 2], bfr[j >> 1][(j & 1) * 2 + 1]);
}

// ================= THE fused per-iteration kernel =================
// grid (4, 1, 128): x = row tile, z = (c,b). 256 threads, 8 warps (2x4), warp 64x32.
// Phase 1: O = softmax_masked(scores) @ emb   (A generated in smem, row sums free)
// Phase 2: H = relu(O @ W1)
// Phase 3: E = tanh(lit + H @ W2) -> g_embh; also next-iter ah1/ah2; last iter: col sums -> g_mid
#define SM_FLOATS 1664   // s_ah1 128 | s_iZ 128 | s_ah2 512 | s_red 256 | s_sd1 128 | s_sd2 128 | s_col 128 | s_w1v 128 | s_w2v 128
#define OFF_XL   (SM_FLOATS*4)            // 6656
#define OFF_AS   (OFF_XL + 128*136*2)     // 41472
#define OFF_BS   (OFF_AS + 128*40*2)      // 51712
#define SMEMSZ   (OFF_BS + 2*32*136*2)    // 69120

__global__ void __launch_bounds__(256, 2) fused_k(
    const float* __restrict__ cw1, const float* __restrict__ cb1,
    const float* __restrict__ cw2, const float* __restrict__ cb2,
    const float* __restrict__ lw1, const float* __restrict__ lb1,
    const float* __restrict__ lw2, const float* __restrict__ lb2,
    int last)
{
    extern __shared__ __align__(16) char dyn[];
    float* s_ah1 = (float*)dyn;
    float* s_iZ  = s_ah1 + 128;
    float* s_ah2 = s_iZ + 128;
    float* s_red = s_ah2 + 512;
    float* s_sd1 = s_red + 256;
    float* s_sd2 = s_sd1 + 128;
    float* s_col = s_sd2 + 128;
    float* s_w1v = s_col + 128;
    float* s_w2v = s_w1v + 128;
    __half* XL = (__half*)(dyn + OFF_XL);      // 128x136: Os then Hs; overlaid by mask in phase 1
    unsigned* s_mask = (unsigned*)XL;          // 128x16 words (8KB)
    __half* As = (__half*)(dyn + OFF_AS);      // 128x40 P chunk
    __half* Bsp = (__half*)(dyn + OFF_BS);     // 2 x 32x136

    const int z = blockIdx.z;
    const int c = z >> 5, b = z & 31;
    const int rowBase = blockIdx.x * 128;
    const int rowOff = b * NN + rowBase;
    const int tid = threadIdx.x, warp = tid >> 5, lane = tid & 31;
    const int wm = (warp >> 2) * 64, wn = (warp & 3) * 32;

    // ---------- prologue ----------
    const float* w1src = (c & 1) ? lw1 : cw1;
    const float* w2src = (c & 1) ? lw2 : cw2;
    if (tid < 128) {
        s_ah1[tid] = g_ah1[c][rowOff + tid];
        s_w1v[tid] = w1src[tid];
        s_w2v[tid] = w2src[tid];
        ((float4*)s_ah2)[tid] = ((const float4*)(g_ah2[c] + b * NN))[tid];
    }
    {
        const uint4* msrc = (const uint4*)(g_mask[c] + (long long)rowOff * 16);
        uint4* mdst = (uint4*)s_mask;
        mdst[tid] = msrc[tid];
        mdst[tid + 256] = msrc[tid + 256];
    }
    __syncthreads();

    const int br = tid >> 4, bs4 = tid & 15;
    auto loadB = [&](const __half* src, int krow0, int stg) {
#pragma unroll
        for (int i = 0; i < 2; i++) {
            int r = br + i * 16;
            cpasync16(sptr(Bsp + stg * 4352 + r * 136 + bs4 * 8),
                      src + (long long)(krow0 + r) * 128 + bs4 * 8);
        }
        asm volatile("cp.async.commit_group;\n");
    };

    float acc[4][4][4];
#pragma unroll
    for (int mi = 0; mi < 4; mi++)
#pragma unroll
        for (int j = 0; j < 4; j++)
#pragma unroll
            for (int q = 0; q < 4; q++) acc[mi][j][q] = 0.f;

    // ---------- phase 1: O = P @ emb, K=512, 16 chunks ----------
    const __half* Bp = g_embh + (long long)z * (NN * EE);
    const int gr = tid >> 1, j0 = (tid & 1) * 16;
    const float a1v = s_ah1[gr];
    float psum = 0.f;

    loadB(Bp, 0, 0);
    for (int ch = 0; ch < 16; ch++) {
        // generate P chunk -> As (16 values per thread), accumulate row-sum partial
        unsigned mw = s_mask[gr * 16 + ch] >> j0;
        const float4* a2 = (const float4*)(s_ah2 + ch * 32 + j0);
        __half2 hv[8];
#pragma unroll
        for (int q = 0; q < 4; q++) {
            float4 v = a2[q];
            float vv[4] = {v.x, v.y, v.z, v.w};
            float p[4];
#pragma unroll
            for (int t = 0; t < 4; t++) {
                float s = a1v + vv[t];
                s = s > 0.f ? s : 0.2f * s;
                float e = ex2a(fminf(s, 10.f) * L2E);
                p[t] = ((mw >> (q * 4 + t)) & 1u) ? e : 0.f;
                psum += p[t];
            }
            hv[q * 2 + 0] = __floats2half2_rn(p[0], p[1]);
            hv[q * 2 + 1] = __floats2half2_rn(p[2], p[3]);
        }
        *(uint4*)(As + gr * 40 + j0) = *(uint4*)&hv[0];
        *(uint4*)(As + gr * 40 + j0 + 8) = *(uint4*)&hv[4];

        if (ch < 15) {
            loadB(Bp, (ch + 1) * 32, (ch + 1) & 1);
            asm volatile("cp.async.wait_group 1;\n");
        } else {
            asm volatile("cp.async.wait_group 0;\n");
        }
        __syncthreads();
        const __half* bs_ = Bsp + (ch & 1) * 4352;
#pragma unroll
        for (int ks = 0; ks < 2; ks++)
            mma_ks(As, 40, ks * 16, bs_, ks, wm, wn, lane, acc);
        __syncthreads();
    }

    // row sums -> iZ
    s_red[tid] = psum;
    __syncthreads();
    if (tid < 128) {
        float s2 = s_red[2 * tid] + s_red[2 * tid + 1];
        s_iZ[tid] = (s2 > 0.f) ? 1.f / s2 : 0.f;
    }
    __syncthreads();

    // normalize, store O (fp16) into XL (mask dead now)
#pragma unroll
    for (int mi = 0; mi < 4; mi++)
#pragma unroll
        for (int h = 0; h < 2; h++) {
            const int r = wm + mi * 16 + (lane >> 2) + h * 8;
            const float rs = s_iZ[r];
#pragma unroll
            for (int j = 0; j < 4; j++) {
                const int c0 = wn + j * 8 + (lane & 3) * 2;
                *(__half2*)(XL + r * 136 + c0) =
                    __floats2half2_rn(acc[mi][j][h * 2] * rs, acc[mi][j][h * 2 + 1] * rs);
            }
        }
    __syncthreads();

    // ---------- phase 2: H = relu(O @ W1), K=128, 4 chunks ----------
#pragma unroll
    for (int mi = 0; mi < 4; mi++)
#pragma unroll
        for (int j = 0; j < 4; j++)
#pragma unroll
            for (int q = 0; q < 4; q++) acc[mi][j][q] = 0.f;
    loadB(g_w1h, 0, 0);
    for (int ch = 0; ch < 4; ch++) {
        if (ch < 3) {
            loadB(g_w1h, (ch + 1) * 32, (ch + 1) & 1);
            asm volatile("cp.async.wait_group 1;\n");
        } else {
            asm volatile("cp.async.wait_group 0;\n");
        }
        __syncthreads();
        const __half* bs_ = Bsp + (ch & 1) * 4352;
#pragma unroll
        for (int ks = 0; ks < 2; ks++)
            mma_ks(XL, 136, ch * 32 + ks * 16, bs_, ks, wm, wn, lane, acc);
        __syncthreads();
    }
    // relu -> H into XL (all mma reads of O are done: barrier above)
#pragma unroll
    for (int mi = 0; mi < 4; mi++)
#pragma unroll
        for (int h = 0; h < 2; h++) {
            const int r = wm + mi * 16 + (lane >> 2) + h * 8;
#pragma unroll
            for (int j = 0; j < 4; j++) {
                const int c0 = wn + j * 8 + (lane & 3) * 2;
                *(__half2*)(XL + r * 136 + c0) =
                    __floats2half2_rn(fmaxf(acc[mi][j][h * 2], 0.f),
                                      fmaxf(acc[mi][j][h * 2 + 1], 0.f));
            }
        }
    if (tid < 128) { s_sd1[tid] = 0.f; s_sd2[tid] = 0.f; s_col[tid] = 0.f; }

    // ---------- phase 3: E = tanh(lit + H @ W2) ----------
#pragma unroll
    for (int mi = 0; mi < 4; mi++)
#pragma unroll
        for (int j = 0; j < 4; j++)
#pragma unroll
            for (int q = 0; q < 4; q++) acc[mi][j][q] = 0.f;
    loadB(g_w2h, 0, 0);
    for (int ch = 0; ch < 4; ch++) {
        if (ch < 3) {
            loadB(g_w2h, (ch + 1) * 32, (ch + 1) & 1);
            asm volatile("cp.async.wait_group 1;\n");
        } else {
            asm volatile("cp.async.wait_group 0;\n");
        }
        __syncthreads();
        const __half* bs_ = Bsp + (ch & 1) * 4352;
#pragma unroll
        for (int ks = 0; ks < 2; ks++)
            mma_ks(XL, 136, ch * 32 + ks * 16, bs_, ks, wm, wn, lane, acc);
        __syncthreads();
    }

    // epilogue: tanh + residual, write fp16 emb, score dots, optional col sums
    const float* litp = g_lit[c >> 1] + ((long long)(b * NN + rowBase)) * EE;
    __half* embp = g_embh + (long long)z * (NN * EE) + (long long)rowBase * EE;
    float colacc[8];
#pragma unroll
    for (int q = 0; q < 8; q++) colacc[q] = 0.f;
#pragma unroll
    for (int mi = 0; mi < 4; mi++)
#pragma unroll
        for (int h = 0; h < 2; h++) {
            const int r = wm + mi * 16 + (lane >> 2) + h * 8;
            float d1 = 0.f, d2 = 0.f;
#pragma unroll
            for (int j = 0; j < 4; j++) {
                const int c0 = wn + j * 8 + (lane & 3) * 2;
                float2 l = *(const float2*)(litp + (long long)r * EE + c0);
                float x0 = tanhf(l.x + acc[mi][j][h * 2]);
                float x1 = tanhf(l.y + acc[mi][j][h * 2 + 1]);
                *(__half2*)(embp + (long long)r * EE + c0) = __floats2half2_rn(x0, x1);
                d1 = fmaf(x0, s_w1v[c0], fmaf(x1, s_w1v[c0 + 1], d1));
                d2 = fmaf(x0, s_w2v[c0], fmaf(x1, s_w2v[c0 + 1], d2));
                colacc[j * 2 + 0] += x0;
                colacc[j * 2 + 1] += x1;
            }
            atomicAdd(&s_sd1[r], d1);
            atomicAdd(&s_sd2[r], d2);
        }
    if (last) {
#pragma unroll
        for (int j = 0; j < 4; j++) {
            const int c0 = wn + j * 8 + (lane & 3) * 2;
            atomicAdd(&s_col[c0], colacc[j * 2]);
            atomicAdd(&s_col[c0 + 1], colacc[j * 2 + 1]);
        }
    }
    __syncthreads();
    if (tid < 128) {
        const float b1 = ((c & 1) ? lb1 : cb1)[0];
        const float b2 = ((c & 1) ? lb2 : cb2)[0];
        g_ah1[c][rowOff + tid] = s_sd1[tid] + b1;
        g_ah2[c][rowOff + tid] = s_sd2[tid] + b2;
        if (last)
            atomicAdd(&g_mid[c >> 1][b * 3 * EE + (c & 1) * EE + tid], s_col[tid]);
    }
}

// ---------------- FFMA SGEMM for one-time setup GEMMs ----------------
template<int EPI>
__global__ void __launch_bounds__(256) sgemm(
    const float* __restrict__ A, const float* __restrict__ Bm, float* __restrict__ C,
    int M, int Nn, int K, const float* __restrict__ extra)
{
    constexpr int BM = 128, BNt = 128, BK = 8, TM = 8, TN = 8;
    __shared__ float As[BK][BM];
    __shared__ float Bs[BK][BNt];
    const int rowBase = blockIdx.x * BM;
    const int colBase = blockIdx.y * BNt;
    const int tid = threadIdx.x;
    const int tx = tid & 15, ty = tid >> 4;
    const int aRow = tid >> 1, aCol = (tid & 1) * 4;
    const int bRow = tid >> 5, bCol = (tid & 31) * 4;

    float acc[TM][TN];
#pragma unroll
    for (int i = 0; i < TM; i++)
#pragma unroll
        for (int j = 0; j < TN; j++) acc[i][j] = 0.f;

    const float* Aptr = A + (long long)(rowBase + aRow) * K + aCol;
    const float* Bptr = Bm + (long long)bRow * Nn + colBase + bCol;

    for (int k0 = 0; k0 < K; k0 += BK) {
        float4 av = *(const float4*)(Aptr + k0);
        float4 bv = *(const float4*)(Bptr + (long long)k0 * Nn);
        As[aCol + 0][aRow] = av.x;
        As[aCol + 1][aRow] = av.y;
        As[aCol + 2][aRow] = av.z;
        As[aCol + 3][aRow] = av.w;
        *(float4*)&Bs[bRow][bCol] = bv;
        __syncthreads();
#pragma unroll
        for (int k = 0; k < BK; k++) {
            float ra[TM], rb[TN];
            *(float4*)&ra[0] = *(const float4*)&As[k][ty * TM];
            *(float4*)&ra[4] = *(const float4*)&As[k][ty * TM + 4];
            *(float4*)&rb[0] = *(const float4*)&Bs[k][tx * TN];
            *(float4*)&rb[4] = *(const float4*)&Bs[k][tx * TN + 4];
#pragma unroll
            for (int i = 0; i < TM; i++)
#pragma unroll
                for (int j = 0; j < TN; j++)
                    acc[i][j] = fmaf(ra[i], rb[j], acc[i][j]);
        }
        __syncthreads();
    }
#pragma unroll
    for (int i = 0; i < TM; i++) {
        int row = rowBase + ty * TM + i;
        float* crow = C + (long long)row * Nn + colBase + tx * TN;
#pragma unroll
        for (int j0 = 0; j0 < TN; j0 += 4) {
            float vv[4];
#pragma unroll
            for (int q = 0; q < 4; q++) {
                float x = acc[i][j0 + q];
                if (EPI == 3) x = x + extra[colBase + tx * TN + j0 + q];
                vv[q] = x;
            }
            float4 v; v.x = vv[0]; v.y = vv[1]; v.z = vv[2]; v.w = vv[3];
            *(float4*)(crow + j0) = v;
        }
    }
}

// ---------------- initial attention row scores (iter 0 only) ----------------
__global__ void __launch_bounds__(256) scores_k(
    const float* __restrict__ cw1, const float* __restrict__ cb1,
    const float* __restrict__ cw2, const float* __restrict__ cb2,
    const float* __restrict__ lw1, const float* __restrict__ lb1,
    const float* __restrict__ lw2, const float* __restrict__ lb2)
{
    const int warp = threadIdx.x >> 5, lane = threadIdx.x & 31;
    const long long gid = (long long)blockIdx.x * 8 + warp;   // < 4*BN
    const int c = (int)(gid >> 14);
    const int rem = (int)(gid & 16383);
    const float* w1 = (c & 1) ? lw1 : cw1;
    const float* w2 = (c & 1) ? lw2 : cw2;
    const float* emb = g_emb[c] + (long long)rem * EE;
    float4 e = ((const float4*)emb)[lane];
    float4 a = ((const float4*)w1)[lane];
    float4 w = ((const float4*)w2)[lane];
    float d1 = e.x * a.x + e.y * a.y + e.z * a.z + e.w * a.w;
    float d2 = e.x * w.x + e.y * w.y + e.z * w.z + e.w * w.w;
#pragma unroll
    for (int o = 16; o; o >>= 1) {
        d1 += __shfl_xor_sync(0xffffffffu, d1, o);
        d2 += __shfl_xor_sync(0xffffffffu, d2, o);
    }
    if (lane == 0) {
        g_ah1[c][rem] = d1 + ((c & 1) ? lb1 : cb1)[0];
        g_ah2[c][rem] = d2 + ((c & 1) ? lb2 : cb2)[0];
    }
}

// ---------------- G -> bitmask ----------------
__global__ void __launch_bounds__(256) mask_k(
    const int* __restrict__ g0, const int* __restrict__ g1,
    const int* __restrict__ g2, const int* __restrict__ g3)
{
    const long long gid = ((long long)blockIdx.x * 256 + threadIdx.x) >> 5;
    const int lane = threadIdx.x & 31;
    const int c = (int)(gid >> 18);
    const long long r = gid & 262143;
    const long long rowrem = r >> 4;
    const int w = (int)(r & 15);
    const int* G = (c == 0) ? g0 : (c == 1) ? g1 : (c == 2) ? g2 : g3;
    int val = G[rowrem * NN + w * 32 + lane];
    unsigned m = __ballot_sync(0xffffffffu, val != 0);
    if (lane == 0) g_mask[c][rowrem * 16 + w] = m;
}

// ---------------- emb init: relu(lit) -> fp32 + fp16; also zero g_mid ----------------
__global__ void __launch_bounds__(1024) init_emb_k()
{
    const long long idx = (long long)blockIdx.x * 1024 + threadIdx.x; // < 4*BNE
    const int c = (int)(idx / BNE);
    const long long off = idx % BNE;
    float v = fmaxf(g_lit[c >> 1][off], 0.f);
    g_emb[c][off] = v;
    g_embh[idx] = __float2half_rn(v);
    if (idx < 2 * BB * 3 * EE) ((float*)g_mid)[idx] = 0.f;
}

// ---------------- mlp weights -> fp16 ----------------
__global__ void __launch_bounds__(256) w16_k(const float* __restrict__ m1,
                                             const float* __restrict__ m2)
{
    int i = blockIdx.x * 256 + threadIdx.x;
    if (i < EE * EE) g_w1h[i] = __float2half_rn(m1[i]);
    else g_w2h[i - EE * EE] = __float2half_rn(m2[i - EE * EE]);
}

// ---------------- rk transpose ----------------
__global__ void __launch_bounds__(256) transpose_rk_k(
    const float* __restrict__ rk1, const float* __restrict__ rk2)
{
    const int idx = blockIdx.x * 256 + threadIdx.x;
    const int s = idx / (3 * EE * EE);
    const int r = idx % (3 * EE * EE);
    const int j = r / EE, k = r % EE;
    const float* rk = s ? rk2 : rk1;
    g_rkT[s][r] = rk[k * 3 * EE + j];
}

// ---------------- GRU (reset_after) ----------------
__global__ void __launch_bounds__(384) gru_k(const float* __restrict__ b1,
                                             const float* __restrict__ b2)
{
    const int s = blockIdx.x >> 5, b = blockIdx.x & 31;
    const float* xz = g_xz[s] + (long long)b * TT * 3 * EE;
    const float4* w4 = (const float4*)(g_rkT[s] + (long long)threadIdx.x * EE);
    const float* br = (s ? b2 : b1) + 3 * EE;
    __shared__ __align__(16) float hs[EE];
    __shared__ float hzs[3 * EE];
    const int j = threadIdx.x;
    if (j < EE) hs[j] = 0.f;
    __syncthreads();
    const float brj = br[j];
    for (int t = 0; t < TT; t++) {
        const float4* h4 = (const float4*)hs;
        float a0 = 0.f, a1 = 0.f, a2 = 0.f, a3 = 0.f;
#pragma unroll
        for (int q = 0; q < 32; q += 4) {
            float4 w, h;
            w = w4[q + 0]; h = h4[q + 0];
            a0 = fmaf(w.x, h.x, a0); a0 = fmaf(w.y, h.y, a0); a0 = fmaf(w.z, h.z, a0); a0 = fmaf(w.w, h.w, a0);
            w = w4[q + 1]; h = h4[q + 1];
            a1 = fmaf(w.x, h.x, a1); a1 = fmaf(w.y, h.y, a1); a1 = fmaf(w.z, h.z, a1); a1 = fmaf(w.w, h.w, a1);
            w = w4[q + 2]; h = h4[q + 2];
            a2 = fmaf(w.x, h.x, a2); a2 = fmaf(w.y, h.y, a2); a2 = fmaf(w.z, h.z, a2); a2 = fmaf(w.w, h.w, a2);
            w = w4[q + 3]; h = h4[q + 3];
            a3 = fmaf(w.x, h.x, a3); a3 = fmaf(w.y, h.y, a3); a3 = fmaf(w.z, h.z, a3); a3 = fmaf(w.w, h.w, a3);
        }
        hzs[j] = (a0 + a1) + (a2 + a3) + brj;
        __syncthreads();
        float hn = 0.f;
        if (j < EE) {
            const float* xzt = xz + t * 3 * EE;
            float zz = 1.f / (1.f + __expf(-(xzt[j] + hzs[j])));
            float rr = 1.f / (1.f + __expf(-(xzt[EE + j] + hzs[EE + j])));
            float hh = tanhf(xzt[2 * EE + j] + rr * hzs[2 * EE + j]);
            hn = zz * hs[j] + (1.f - zz) * hh;
        }
        __syncthreads();
        if (j < EE) hs[j] = hn;
        __syncthreads();
    }
    if (j < EE) g_hfin[s][b * EE + j] = hs[j];
}

// ---------------- graph embedding head (mid from g_mid + g_hfin) ----------------
__global__ void __launch_bounds__(64) outemb_k(const float* __restrict__ Wout,
                                               const float* __restrict__ bout)
{
    const int s = blockIdx.x >> 5, b = blockIdx.x & 31;
    __shared__ float ms[3 * EE];
    for (int k = threadIdx.x; k < 3 * EE; k += 64)
        ms[k] = (k < 2 * EE) ? g_mid[s][b * 3 * EE + k] : g_hfin[s][b * EE + (k - 2 * EE)];
    __syncthreads();
    const int o = threadIdx.x;
    float acc = bout[o];
    for (int k = 0; k < 3 * EE; k++) acc = fmaf(ms[k], Wout[k * OO + o], acc);
    g_gemb[s][b * OO + o] = acc;
}

// ---------------- cosine head ----------------
__global__ void __launch_bounds__(64) final_k(float* __restrict__ out)
{
    const int b = blockIdx.x, t = threadIdx.x;
    float x = g_gemb[0][b * OO + t], y = g_gemb[1][b * OO + t];
    float d = x * y, nx = x * x, ny = y * y;
    __shared__ float sd[2], sx[2], sy[2];
#pragma unroll
    for (int o = 16; o; o >>= 1) {
        d  += __shfl_xor_sync(0xffffffffu, d, o);
        nx += __shfl_xor_sync(0xffffffffu, nx, o);
        ny += __shfl_xor_sync(0xffffffffu, ny, o);
    }
    if ((t & 31) == 0) { sd[t >> 5] = d; sx[t >> 5] = nx; sy[t >> 5] = ny; }
    __syncthreads();
    if (t == 0) {
        float D = sd[0] + sd[1], X = sx[0] + sx[1], Y = sy[0] + sy[1];
        float cosv = D * rsqrtf(fmaxf(X, 1e-12f)) * rsqrtf(fmaxf(Y, 1e-12f));
        out[b] = (cosv + 1.f) * 0.5f;
    }
}

// ---------------- launch ----------------
extern "C" void kernel_launch(void* const* d_in, const int* in_sizes, int n_in,
                              void* d_out, int out_size)
{
    const int*   CFG1 = (const int*)d_in[0];
    const int*   LFG1 = (const int*)d_in[1];
    const float* LIT1 = (const float*)d_in[2];
    const float* SEM1 = (const float*)d_in[3];
    const int*   CFG2 = (const int*)d_in[4];
    const int*   LFG2 = (const int*)d_in[5];
    const float* LIT2 = (const float*)d_in[6];
    const float* SEM2 = (const float*)d_in[7];
    const float* Wl1  = (const float*)d_in[8];
    const float* g1k  = (const float*)d_in[9];
    const float* g1rk = (const float*)d_in[10];
    const float* g1b  = (const float*)d_in[11];
    const float* Wl2  = (const float*)d_in[12];
    const float* g2k  = (const float*)d_in[13];
    const float* g2rk = (const float*)d_in[14];
    const float* g2b  = (const float*)d_in[15];
    const float* cw1  = (const float*)d_in[16];
    const float* cb1  = (const float*)d_in[17];
    const float* cw2  = (const float*)d_in[18];
    const float* cb2  = (const float*)d_in[19];
    const float* lw1  = (const float*)d_in[20];
    const float* lb1  = (const float*)d_in[21];
    const float* lw2  = (const float*)d_in[22];
    const float* lb2  = (const float*)d_in[23];
    const float* mlp1 = (const float*)d_in[24];
    const float* mlp2 = (const float*)d_in[25];
    const float* Wout = (const float*)d_in[26];
    const float* bout = (const float*)d_in[27];

    float *p_lit, *p_xz;
    cudaGetSymbolAddress((void**)&p_lit, g_lit);
    cudaGetSymbolAddress((void**)&p_xz, g_xz);

    cudaFuncSetAttribute(fused_k, cudaFuncAttributeMaxDynamicSharedMemorySize, SMEMSZ);

    // one-time setup
    mask_k<<<131072, 256>>>(CFG1, LFG1, CFG2, LFG2);
    sgemm<0><<<dim3(BN / 128, 1, 1), 256>>>(LIT1, Wl1, p_lit,       BN, EE, EE, nullptr);
    sgemm<0><<<dim3(BN / 128, 1, 1), 256>>>(LIT2, Wl2, p_lit + BNE, BN, EE, EE, nullptr);
    init_emb_k<<<8192, 1024>>>();
    sgemm<3><<<dim3(BB * TT / 128, 3, 1), 256>>>(SEM1, g1k, p_xz,                    BB * TT, 3 * EE, EE, g1b);
    sgemm<3><<<dim3(BB * TT / 128, 3, 1), 256>>>(SEM2, g2k, p_xz + BB * TT * 3 * EE, BB * TT, 3 * EE, EE, g2b);
    transpose_rk_k<<<2 * 3 * EE * EE / 256, 256>>>(g1rk, g2rk);
    gru_k<<<64, 384>>>(g1b, g2b);
    w16_k<<<2 * EE * EE / 256, 256>>>(mlp1, mlp2);
    scores_k<<<4 * BN / 8, 256>>>(cw1, cb1, cw2, cb2, lw1, lb1, lw2, lb2);

    // 5 iterations, one fused kernel each
    for (int it = 0; it < NITER; it++) {
        fused_k<<<dim3(4, 1, 128), 256, SMEMSZ>>>(
            cw1, cb1, cw2, cb2, lw1, lb1, lw2, lb2, (it == NITER - 1) ? 1 : 0);
    }

    outemb_k<<<2 * BB, 64>>>(Wout, bout);
    final_k<<<BB, 64>>>((float*)d_out);
}

// round 4
// speedup vs baseline: 2.7631x; 1.0270x over previous
#include <cuda_runtime.h>
#include <cuda_fp16.h>
#include <math.h>

#define BB 32
#define NN 512
#define TT 64
#define EE 128
#define OO 64
#define NITER 5
#define BNE (BB*NN*EE)      // 2,097,152 = 2^21
#define BN  (BB*NN)         // 16,384
#define L2E 1.442695040888963f

// ---------------- scratch (device globals; no allocation allowed) ----------------
__device__ float    g_lit[2][BNE];
__device__ float    g_ah1[4][BN];
__device__ float    g_ah2[4][BN];
__device__ unsigned g_mask[4][BN*(NN/32)];
__device__ float    g_xz[2][BB*TT*3*EE];
__device__ float    g_hfin[2][BB*EE];
__device__ float    g_rkT[2][3*EE*EE];
__device__ float    g_mid[2][BB*3*EE];
__device__ float    g_gemb[2][BB*OO];
__device__ __half   g_embh[4ll*BNE];
__device__ __half   g_w1h[EE*EE];
__device__ __half   g_w2h[EE*EE];

// ================= helpers =================
__device__ __forceinline__ unsigned sptr(const void* p) {
    return (unsigned)__cvta_generic_to_shared(p);
}
__device__ __forceinline__ void cpasync16(unsigned s, const void* g) {
    asm volatile("cp.async.cg.shared.global [%0], [%1], 16;\n" :: "r"(s), "l"(g));
}
__device__ __forceinline__ void ldsm4(unsigned* r, unsigned addr) {
    asm volatile("ldmatrix.sync.aligned.m8n8.x4.shared.b16 {%0,%1,%2,%3},[%4];\n"
                 : "=r"(r[0]), "=r"(r[1]), "=r"(r[2]), "=r"(r[3]) : "r"(addr));
}
__device__ __forceinline__ void ldsm4t(unsigned* r, unsigned addr) {
    asm volatile("ldmatrix.sync.aligned.m8n8.x4.trans.shared.b16 {%0,%1,%2,%3},[%4];\n"
                 : "=r"(r[0]), "=r"(r[1]), "=r"(r[2]), "=r"(r[3]) : "r"(addr));
}
__device__ __forceinline__ void mma16816(float* d, const unsigned* a, unsigned b0, unsigned b1) {
    asm volatile(
        "mma.sync.aligned.m16n8k16.row.col.f32.f16.f16.f32 "
        "{%0,%1,%2,%3},{%4,%5,%6,%7},{%8,%9},{%0,%1,%2,%3};\n"
        : "+f"(d[0]), "+f"(d[1]), "+f"(d[2]), "+f"(d[3])
        : "r"(a[0]), "r"(a[1]), "r"(a[2]), "r"(a[3]), "r"(b0), "r"(b1));
}
__device__ __forceinline__ float ex2a(float x) {
    float y; asm("ex2.approx.f32 %0,%1;\n" : "=f"(y) : "f"(x)); return y;
}
__device__ __forceinline__ float tanha(float x) {
    float y; asm("tanh.approx.f32 %0,%1;\n" : "=f"(y) : "f"(x)); return y;
}

// one k=16 mma step
__device__ __forceinline__ void mma_ks(const __half* as_, int astr, int aoff,
                                       const __half* bs_, int ks,
                                       int wm, int wn, int lane, float acc[4][4][4])
{
    unsigned a[4][4], bfr[2][4];
#pragma unroll
    for (int mi = 0; mi < 4; mi++)
        ldsm4(a[mi], sptr(as_ + (wm + mi * 16 + (lane & 15)) * astr + aoff + (lane >> 4) * 8));
#pragma unroll
    for (int nb = 0; nb < 2; nb++)
        ldsm4t(bfr[nb], sptr(bs_ + (ks * 16 + (lane & 15)) * 136 + wn + nb * 16 + (lane >> 4) * 8));
#pragma unroll
    for (int mi = 0; mi < 4; mi++)
#pragma unroll
        for (int j = 0; j < 4; j++)
            mma16816(acc[mi][j], a[mi], bfr[j >> 1][(j & 1) * 2], bfr[j >> 1][(j & 1) * 2 + 1]);
}

// ================= fused per-iteration kernel =================
// grid (4,1,128), 256 thr, 8 warps (2x4), warp 64x32.
// smem layout (bytes):
//   floats: 1664*4 = 6656
//   XL  : 128*136*2 = 34816          (mask overlay in phase 1)
//   As  : 3 * 128*40*2 = 30720       (triple-buffered generated P)
//   Bs  : 3 * 32*136*2 = 26112      (triple-buffered cp.async B)
#define OFF_XL   6656
#define OFF_AS   (OFF_XL + 34816)     // 41472
#define OFF_BS   (OFF_AS + 30720)     // 72192
#define SMEMSZ   (OFF_BS + 26112)     // 98304

__global__ void __launch_bounds__(256, 2) fused_k(
    const float* __restrict__ cw1, const float* __restrict__ cb1,
    const float* __restrict__ cw2, const float* __restrict__ cb2,
    const float* __restrict__ lw1, const float* __restrict__ lb1,
    const float* __restrict__ lw2, const float* __restrict__ lb2,
    int last)
{
    extern __shared__ __align__(16) char dyn[];
    float* s_ah1 = (float*)dyn;
    float* s_iZ  = s_ah1 + 128;
    float* s_ah2 = s_iZ + 128;
    float* s_red = s_ah2 + 512;
    float* s_sd1 = s_red + 256;
    float* s_sd2 = s_sd1 + 128;
    float* s_col = s_sd2 + 128;
    float* s_w1v = s_col + 128;
    float* s_w2v = s_w1v + 128;
    __half* XL = (__half*)(dyn + OFF_XL);
    unsigned* s_mask = (unsigned*)XL;          // 128x16 words in phase 1
    __half* Asp = (__half*)(dyn + OFF_AS);     // 3 x (128x40)
    __half* Bsp = (__half*)(dyn + OFF_BS);     // 3 x (32x136)

    const int z = blockIdx.z;
    const int c = z >> 5, b = z & 31;
    const int rowBase = blockIdx.x * 128;
    const int rowOff = b * NN + rowBase;
    const int tid = threadIdx.x, warp = tid >> 5, lane = tid & 31;
    const int wm = (warp >> 2) * 64, wn = (warp & 3) * 32;

    // ---------- prologue: stage row data ----------
    const float* w1src = (c & 1) ? lw1 : cw1;
    const float* w2src = (c & 1) ? lw2 : cw2;
    if (tid < 128) {
        s_ah1[tid] = g_ah1[c][rowOff + tid];
        s_w1v[tid] = w1src[tid];
        s_w2v[tid] = w2src[tid];
        ((float4*)s_ah2)[tid] = ((const float4*)(g_ah2[c] + b * NN))[tid];
    }
    {
        const uint4* msrc = (const uint4*)(g_mask[c] + (long long)rowOff * 16);
        uint4* mdst = (uint4*)s_mask;
        mdst[tid] = msrc[tid];
        mdst[tid + 256] = msrc[tid + 256];
    }
    __syncthreads();

    const int br = tid >> 4, bs4 = tid & 15;
    auto loadB = [&](const __half* src, int krow0, int stg) {
#pragma unroll
        for (int i = 0; i < 2; i++) {
            int r = br + i * 16;
            cpasync16(sptr(Bsp + stg * 4352 + r * 136 + bs4 * 8),
                      src + (long long)(krow0 + r) * 128 + bs4 * 8);
        }
        asm volatile("cp.async.commit_group;\n");
    };

    const int gr = tid >> 1, j0 = (tid & 1) * 16;
    const float a1v = s_ah1[gr];
    float psum = 0.f;
    auto genP = [&](int ch, int stg) {
        unsigned mw = s_mask[gr * 16 + ch] >> j0;
        const float4* a2 = (const float4*)(s_ah2 + ch * 32 + j0);
        __half2 hv[8];
#pragma unroll
        for (int q = 0; q < 4; q++) {
            float4 v = a2[q];
            float vv[4] = {v.x, v.y, v.z, v.w};
            float p[4];
#pragma unroll
            for (int t = 0; t < 4; t++) {
                float s = a1v + vv[t];
                s = s > 0.f ? s : 0.2f * s;
                float e = ex2a(fminf(s, 10.f) * L2E);
                p[t] = ((mw >> (q * 4 + t)) & 1u) ? e : 0.f;
                psum += p[t];
            }
            hv[q * 2 + 0] = __floats2half2_rn(p[0], p[1]);
            hv[q * 2 + 1] = __floats2half2_rn(p[2], p[3]);
        }
        __half* as = Asp + stg * 5120;
        *(uint4*)(as + gr * 40 + j0) = *(uint4*)&hv[0];
        *(uint4*)(as + gr * 40 + j0 + 8) = *(uint4*)&hv[4];
    };

    float acc[4][4][4];
#pragma unroll
    for (int mi = 0; mi < 4; mi++)
#pragma unroll
        for (int j = 0; j < 4; j++)
#pragma unroll
            for (int q = 0; q < 4; q++) acc[mi][j][q] = 0.f;

    // ---------- phase 1: O = P @ emb, K=512, 16 chunks, 1 barrier/chunk ----------
    const __half* Bp = g_embh + (long long)z * (NN * EE);
    loadB(Bp, 0, 0);
    loadB(Bp, 32, 1);
    genP(0, 0);
    genP(1, 1);
    asm volatile("cp.async.wait_group 1;\n");
    __syncthreads();
#pragma unroll 4
    for (int ch = 0; ch < 16; ch++) {
        if (ch + 2 < 16) {
            loadB(Bp, (ch + 2) * 32, (ch + 2) % 3);
            genP(ch + 2, (ch + 2) % 3);
        }
        const __half* as = Asp + (ch % 3) * 5120;
        const __half* bs_ = Bsp + (ch % 3) * 4352;
#pragma unroll
        for (int ks = 0; ks < 2; ks++)
            mma_ks(as, 40, ks * 16, bs_, ks, wm, wn, lane, acc);
        if (ch + 2 < 16) asm volatile("cp.async.wait_group 1;\n");
        else             asm volatile("cp.async.wait_group 0;\n");
        __syncthreads();
    }

    // row sums -> iZ
    s_red[tid] = psum;
    __syncthreads();
    if (tid < 128) {
        float s2 = s_red[2 * tid] + s_red[2 * tid + 1];
        s_iZ[tid] = (s2 > 0.f) ? __fdividef(1.f, s2) : 0.f;
    }
    __syncthreads();

    // normalize, store O into XL (mask dead now)
#pragma unroll
    for (int mi = 0; mi < 4; mi++)
#pragma unroll
        for (int h = 0; h < 2; h++) {
            const int r = wm + mi * 16 + (lane >> 2) + h * 8;
            const float rs = s_iZ[r];
#pragma unroll
            for (int j = 0; j < 4; j++) {
                const int c0 = wn + j * 8 + (lane & 3) * 2;
                *(__half2*)(XL + r * 136 + c0) =
                    __floats2half2_rn(acc[mi][j][h * 2] * rs, acc[mi][j][h * 2 + 1] * rs);
            }
        }
    __syncthreads();

    // ---------- phase 2: H = relu(O @ W1), K=128 ----------
#pragma unroll
    for (int mi = 0; mi < 4; mi++)
#pragma unroll
        for (int j = 0; j < 4; j++)
#pragma unroll
            for (int q = 0; q < 4; q++) acc[mi][j][q] = 0.f;
    loadB(g_w1h, 0, 0);
    loadB(g_w1h, 32, 1);
    asm volatile("cp.async.wait_group 1;\n");
    __syncthreads();
#pragma unroll
    for (int ch = 0; ch < 4; ch++) {
        if (ch + 2 < 4) loadB(g_w1h, (ch + 2) * 32, (ch + 2) % 3);
        const __half* bs_ = Bsp + (ch % 3) * 4352;
#pragma unroll
        for (int ks = 0; ks < 2; ks++)
            mma_ks(XL, 136, ch * 32 + ks * 16, bs_, ks, wm, wn, lane, acc);
        if (ch + 2 < 4) asm volatile("cp.async.wait_group 1;\n");
        else            asm volatile("cp.async.wait_group 0;\n");
        __syncthreads();
    }
    // relu -> H into XL
#pragma unroll
    for (int mi = 0; mi < 4; mi++)
#pragma unroll
        for (int h = 0; h < 2; h++) {
            const int r = wm + mi * 16 + (lane >> 2) + h * 8;
#pragma unroll
            for (int j = 0; j < 4; j++) {
                const int c0 = wn + j * 8 + (lane & 3) * 2;
                *(__half2*)(XL + r * 136 + c0) =
                    __floats2half2_rn(fmaxf(acc[mi][j][h * 2], 0.f),
                                      fmaxf(acc[mi][j][h * 2 + 1], 0.f));
            }
        }
    if (tid < 128) { s_sd1[tid] = 0.f; s_sd2[tid] = 0.f; s_col[tid] = 0.f; }

    // ---------- phase 3: E = tanh(lit + H @ W2) ----------
#pragma unroll
    for (int mi = 0; mi < 4; mi++)
#pragma unroll
        for (int j = 0; j < 4; j++)
#pragma unroll
            for (int q = 0; q < 4; q++) acc[mi][j][q] = 0.f;
    loadB(g_w2h, 0, 0);
    loadB(g_w2h, 32, 1);
    asm volatile("cp.async.wait_group 1;\n");
    __syncthreads();
#pragma unroll
    for (int ch = 0; ch < 4; ch++) {
        if (ch + 2 < 4) loadB(g_w2h, (ch + 2) * 32, (ch + 2) % 3);
        const __half* bs_ = Bsp + (ch % 3) * 4352;
#pragma unroll
        for (int ks = 0; ks < 2; ks++)
            mma_ks(XL, 136, ch * 32 + ks * 16, bs_, ks, wm, wn, lane, acc);
        if (ch + 2 < 4) asm volatile("cp.async.wait_group 1;\n");
        else            asm volatile("cp.async.wait_group 0;\n");
        __syncthreads();
    }

    // epilogue: tanh (HW approx) + residual, fp16 emb, next-iter score dots, col sums
    const float* litp = g_lit[c >> 1] + ((long long)(b * NN + rowBase)) * EE;
    __half* embp = g_embh + (long long)z * (NN * EE) + (long long)rowBase * EE;
    float colacc[8];
#pragma unroll
    for (int q = 0; q < 8; q++) colacc[q] = 0.f;
#pragma unroll
    for (int mi = 0; mi < 4; mi++)
#pragma unroll
        for (int h = 0; h < 2; h++) {
            const int r = wm + mi * 16 + (lane >> 2) + h * 8;
            float d1 = 0.f, d2 = 0.f;
#pragma unroll
            for (int j = 0; j < 4; j++) {
                const int c0 = wn + j * 8 + (lane & 3) * 2;
                float2 l = *(const float2*)(litp + (long long)r * EE + c0);
                float x0 = tanha(l.x + acc[mi][j][h * 2]);
                float x1 = tanha(l.y + acc[mi][j][h * 2 + 1]);
                *(__half2*)(embp + (long long)r * EE + c0) = __floats2half2_rn(x0, x1);
                d1 = fmaf(x0, s_w1v[c0], fmaf(x1, s_w1v[c0 + 1], d1));
                d2 = fmaf(x0, s_w2v[c0], fmaf(x1, s_w2v[c0 + 1], d2));
                colacc[j * 2 + 0] += x0;
                colacc[j * 2 + 1] += x1;
            }
            atomicAdd(&s_sd1[r], d1);
            atomicAdd(&s_sd2[r], d2);
        }
    if (last) {
#pragma unroll
        for (int j = 0; j < 4; j++) {
            const int c0 = wn + j * 8 + (lane & 3) * 2;
            atomicAdd(&s_col[c0], colacc[j * 2]);
            atomicAdd(&s_col[c0 + 1], colacc[j * 2 + 1]);
        }
    }
    __syncthreads();
    if (tid < 128) {
        const float b1 = ((c & 1) ? lb1 : cb1)[0];
        const float b2 = ((c & 1) ? lb2 : cb2)[0];
        g_ah1[c][rowOff + tid] = s_sd1[tid] + b1;
        g_ah2[c][rowOff + tid] = s_sd2[tid] + b2;
        if (last)
            atomicAdd(&g_mid[c >> 1][b * 3 * EE + (c & 1) * EE + tid], s_col[tid]);
    }
}

// ---------------- FFMA SGEMM for one-time setup GEMMs ----------------
template<int EPI>
__global__ void __launch_bounds__(256) sgemm(
    const float* __restrict__ A, const float* __restrict__ Bm, float* __restrict__ C,
    int M, int Nn, int K, const float* __restrict__ extra)
{
    constexpr int BM = 128, BNt = 128, BK = 8, TM = 8, TN = 8;
    __shared__ float As[BK][BM];
    __shared__ float Bs[BK][BNt];
    const int rowBase = blockIdx.x * BM;
    const int colBase = blockIdx.y * BNt;
    const int tid = threadIdx.x;
    const int tx = tid & 15, ty = tid >> 4;
    const int aRow = tid >> 1, aCol = (tid & 1) * 4;
    const int bRow = tid >> 5, bCol = (tid & 31) * 4;

    float acc[TM][TN];
#pragma unroll
    for (int i = 0; i < TM; i++)
#pragma unroll
        for (int j = 0; j < TN; j++) acc[i][j] = 0.f;

    const float* Aptr = A + (long long)(rowBase + aRow) * K + aCol;
    const float* Bptr = Bm + (long long)bRow * Nn + colBase + bCol;

    for (int k0 = 0; k0 < K; k0 += BK) {
        float4 av = *(const float4*)(Aptr + k0);
        float4 bv = *(const float4*)(Bptr + (long long)k0 * Nn);
        As[aCol + 0][aRow] = av.x;
        As[aCol + 1][aRow] = av.y;
        As[aCol + 2][aRow] = av.z;
        As[aCol + 3][aRow] = av.w;
        *(float4*)&Bs[bRow][bCol] = bv;
        __syncthreads();
#pragma unroll
        for (int k = 0; k < BK; k++) {
            float ra[TM], rb[TN];
            *(float4*)&ra[0] = *(const float4*)&As[k][ty * TM];
            *(float4*)&ra[4] = *(const float4*)&As[k][ty * TM + 4];
            *(float4*)&rb[0] = *(const float4*)&Bs[k][tx * TN];
            *(float4*)&rb[4] = *(const float4*)&Bs[k][tx * TN + 4];
#pragma unroll
            for (int i = 0; i < TM; i++)
#pragma unroll
                for (int j = 0; j < TN; j++)
                    acc[i][j] = fmaf(ra[i], rb[j], acc[i][j]);
        }
        __syncthreads();
    }
#pragma unroll
    for (int i = 0; i < TM; i++) {
        int row = rowBase + ty * TM + i;
        float* crow = C + (long long)row * Nn + colBase + tx * TN;
#pragma unroll
        for (int j0 = 0; j0 < TN; j0 += 4) {
            float vv[4];
#pragma unroll
            for (int q = 0; q < 4; q++) {
                float x = acc[i][j0 + q];
                if (EPI == 3) x = x + extra[colBase + tx * TN + j0 + q];
                vv[q] = x;
            }
            float4 v; v.x = vv[0]; v.y = vv[1]; v.z = vv[2]; v.w = vv[3];
            *(float4*)(crow + j0) = v;
        }
    }
}

// ---------------- initial scores from relu(lit) ----------------
__global__ void __launch_bounds__(256) scores_k(
    const float* __restrict__ cw1, const float* __restrict__ cb1,
    const float* __restrict__ cw2, const float* __restrict__ cb2,
    const float* __restrict__ lw1, const float* __restrict__ lb1,
    const float* __restrict__ lw2, const float* __restrict__ lb2)
{
    const int warp = threadIdx.x >> 5, lane = threadIdx.x & 31;
    const long long gid = (long long)blockIdx.x * 8 + warp;   // < 4*BN
    const int c = (int)(gid >> 14);
    const int rem = (int)(gid & 16383);
    const float* w1 = (c & 1) ? lw1 : cw1;
    const float* w2 = (c & 1) ? lw2 : cw2;
    const float* lit = g_lit[c >> 1] + (long long)rem * EE;
    float4 e = ((const float4*)lit)[lane];
    e.x = fmaxf(e.x, 0.f); e.y = fmaxf(e.y, 0.f);
    e.z = fmaxf(e.z, 0.f); e.w = fmaxf(e.w, 0.f);
    float4 a = ((const float4*)w1)[lane];
    float4 w = ((const float4*)w2)[lane];
    float d1 = e.x * a.x + e.y * a.y + e.z * a.z + e.w * a.w;
    float d2 = e.x * w.x + e.y * w.y + e.z * w.z + e.w * w.w;
#pragma unroll
    for (int o = 16; o; o >>= 1) {
        d1 += __shfl_xor_sync(0xffffffffu, d1, o);
        d2 += __shfl_xor_sync(0xffffffffu, d2, o);
    }
    if (lane == 0) {
        g_ah1[c][rem] = d1 + ((c & 1) ? lb1 : cb1)[0];
        g_ah2[c][rem] = d2 + ((c & 1) ? lb2 : cb2)[0];
    }
}

// ---------------- G -> bitmask ----------------
__global__ void __launch_bounds__(256) mask_k(
    const int* __restrict__ g0, const int* __restrict__ g1,
    const int* __restrict__ g2, const int* __restrict__ g3)
{
    const long long gid = ((long long)blockIdx.x * 256 + threadIdx.x) >> 5;
    const int lane = threadIdx.x & 31;
    const int c = (int)(gid >> 18);
    const long long r = gid & 262143;
    const long long rowrem = r >> 4;
    const int w = (int)(r & 15);
    const int* G = (c == 0) ? g0 : (c == 1) ? g1 : (c == 2) ? g2 : g3;
    int val = G[rowrem * NN + w * 32 + lane];
    unsigned m = __ballot_sync(0xffffffffu, val != 0);
    if (lane == 0) g_mask[c][rowrem * 16 + w] = m;
}

// ---------------- init: embh = fp16(relu(lit)); weights -> fp16; zero g_mid ----------------
__global__ void __launch_bounds__(1024) init_emb_k(const float* __restrict__ m1,
                                                   const float* __restrict__ m2)
{
    const long long idx = (long long)blockIdx.x * 1024 + threadIdx.x; // < 4*BNE
    const int c = (int)(idx >> 21);
    const long long off = idx & (BNE - 1);
    g_embh[idx] = __float2half_rn(fmaxf(g_lit[c >> 1][off], 0.f));
    if (idx < EE * EE) g_w1h[idx] = __float2half_rn(m1[idx]);
    else if (idx < 2 * EE * EE) g_w2h[idx - EE * EE] = __float2half_rn(m2[idx - EE * EE]);
    if (idx < 2 * BB * 3 * EE) ((float*)g_mid)[idx] = 0.f;
}

// ---------------- rk transpose ----------------
__global__ void __launch_bounds__(256) transpose_rk_k(
    const float* __restrict__ rk1, const float* __restrict__ rk2)
{
    const int idx = blockIdx.x * 256 + threadIdx.x;
    const int s = idx / (3 * EE * EE);
    const int r = idx % (3 * EE * EE);
    const int j = r / EE, k = r % EE;
    const float* rk = s ? rk2 : rk1;
    g_rkT[s][r] = rk[k * 3 * EE + j];
}

// ---------------- GRU (reset_after) ----------------
__global__ void __launch_bounds__(384) gru_k(const float* __restrict__ b1,
                                             const float* __restrict__ b2)
{
    const int s = blockIdx.x >> 5, b = blockIdx.x & 31;
    const float* xz = g_xz[s] + (long long)b * TT * 3 * EE;
    const float4* w4 = (const float4*)(g_rkT[s] + (long long)threadIdx.x * EE);
    const float* br = (s ? b2 : b1) + 3 * EE;
    __shared__ __align__(16) float hs[EE];
    __shared__ float hzs[3 * EE];
    const int j = threadIdx.x;
    if (j < EE) hs[j] = 0.f;
    __syncthreads();
    const float brj = br[j];
    for (int t = 0; t < TT; t++) {
        const float4* h4 = (const float4*)hs;
        float a0 = 0.f, a1 = 0.f, a2 = 0.f, a3 = 0.f;
#pragma unroll
        for (int q = 0; q < 32; q += 4) {
            float4 w, h;
            w = w4[q + 0]; h = h4[q + 0];
            a0 = fmaf(w.x, h.x, a0); a0 = fmaf(w.y, h.y, a0); a0 = fmaf(w.z, h.z, a0); a0 = fmaf(w.w, h.w, a0);
            w = w4[q + 1]; h = h4[q + 1];
            a1 = fmaf(w.x, h.x, a1); a1 = fmaf(w.y, h.y, a1); a1 = fmaf(w.z, h.z, a1); a1 = fmaf(w.w, h.w, a1);
            w = w4[q + 2]; h = h4[q + 2];
            a2 = fmaf(w.x, h.x, a2); a2 = fmaf(w.y, h.y, a2); a2 = fmaf(w.z, h.z, a2); a2 = fmaf(w.w, h.w, a2);
            w = w4[q + 3]; h = h4[q + 3];
            a3 = fmaf(w.x, h.x, a3); a3 = fmaf(w.y, h.y, a3); a3 = fmaf(w.z, h.z, a3); a3 = fmaf(w.w, h.w, a3);
        }
        hzs[j] = (a0 + a1) + (a2 + a3) + brj;
        __syncthreads();
        float hn = 0.f;
        if (j < EE) {
            const float* xzt = xz + t * 3 * EE;
            float zz = __fdividef(1.f, 1.f + __expf(-(xzt[j] + hzs[j])));
            float rr = __fdividef(1.f, 1.f + __expf(-(xzt[EE + j] + hzs[EE + j])));
            float hh = tanha(xzt[2 * EE + j] + rr * hzs[2 * EE + j]);
            hn = zz * hs[j] + (1.f - zz) * hh;
        }
        __syncthreads();
        if (j < EE) hs[j] = hn;
        __syncthreads();
    }
    if (j < EE) g_hfin[s][b * EE + j] = hs[j];
}

// ---------------- graph embedding head ----------------
__global__ void __launch_bounds__(64) outemb_k(const float* __restrict__ Wout,
                                               const float* __restrict__ bout)
{
    const int s = blockIdx.x >> 5, b = blockIdx.x & 31;
    __shared__ float ms[3 * EE];
    for (int k = threadIdx.x; k < 3 * EE; k += 64)
        ms[k] = (k < 2 * EE) ? g_mid[s][b * 3 * EE + k] : g_hfin[s][b * EE + (k - 2 * EE)];
    __syncthreads();
    const int o = threadIdx.x;
    float acc = bout[o];
    for (int k = 0; k < 3 * EE; k++) acc = fmaf(ms[k], Wout[k * OO + o], acc);
    g_gemb[s][b * OO + o] = acc;
}

// ---------------- cosine head ----------------
__global__ void __launch_bounds__(64) final_k(float* __restrict__ out)
{
    const int b = blockIdx.x, t = threadIdx.x;
    float x = g_gemb[0][b * OO + t], y = g_gemb[1][b * OO + t];
    float d = x * y, nx = x * x, ny = y * y;
    __shared__ float sd[2], sx[2], sy[2];
#pragma unroll
    for (int o = 16; o; o >>= 1) {
        d  += __shfl_xor_sync(0xffffffffu, d, o);
        nx += __shfl_xor_sync(0xffffffffu, nx, o);
        ny += __shfl_xor_sync(0xffffffffu, ny, o);
    }
    if ((t & 31) == 0) { sd[t >> 5] = d; sx[t >> 5] = nx; sy[t >> 5] = ny; }
    __syncthreads();
    if (t == 0) {
        float D = sd[0] + sd[1], X = sx[0] + sx[1], Y = sy[0] + sy[1];
        float cosv = D * rsqrtf(fmaxf(X, 1e-12f)) * rsqrtf(fmaxf(Y, 1e-12f));
        out[b] = (cosv + 1.f) * 0.5f;
    }
}

// ---------------- launch ----------------
extern "C" void kernel_launch(void* const* d_in, const int* in_sizes, int n_in,
                              void* d_out, int out_size)
{
    const int*   CFG1 = (const int*)d_in[0];
    const int*   LFG1 = (const int*)d_in[1];
    const float* LIT1 = (const float*)d_in[2];
    const float* SEM1 = (const float*)d_in[3];
    const int*   CFG2 = (const int*)d_in[4];
    const int*   LFG2 = (const int*)d_in[5];
    const float* LIT2 = (const float*)d_in[6];
    const float* SEM2 = (const float*)d_in[7];
    const float* Wl1  = (const float*)d_in[8];
    const float* g1k  = (const float*)d_in[9];
    const float* g1rk = (const float*)d_in[10];
    const float* g1b  = (const float*)d_in[11];
    const float* Wl2  = (const float*)d_in[12];
    const float* g2k  = (const float*)d_in[13];
    const float* g2rk = (const float*)d_in[14];
    const float* g2b  = (const float*)d_in[15];
    const float* cw1  = (const float*)d_in[16];
    const float* cb1  = (const float*)d_in[17];
    const float* cw2  = (const float*)d_in[18];
    const float* cb2  = (const float*)d_in[19];
    const float* lw1  = (const float*)d_in[20];
    const float* lb1  = (const float*)d_in[21];
    const float* lw2  = (const float*)d_in[22];
    const float* lb2  = (const float*)d_in[23];
    const float* mlp1 = (const float*)d_in[24];
    const float* mlp2 = (const float*)d_in[25];
    const float* Wout = (const float*)d_in[26];
    const float* bout = (const float*)d_in[27];

    float *p_lit, *p_xz;
    cudaGetSymbolAddress((void**)&p_lit, g_lit);
    cudaGetSymbolAddress((void**)&p_xz, g_xz);

    cudaFuncSetAttribute(fused_k, cudaFuncAttributeMaxDynamicSharedMemorySize, SMEMSZ);

    // launches 1-5: prerequisites of the loop (ncu -s 5 captures launch #6 = fused_k)
    mask_k<<<131072, 256>>>(CFG1, LFG1, CFG2, LFG2);
    sgemm<0><<<dim3(BN / 128, 1, 1), 256>>>(LIT1, Wl1, p_lit,       BN, EE, EE, nullptr);
    sgemm<0><<<dim3(BN / 128, 1, 1), 256>>>(LIT2, Wl2, p_lit + BNE, BN, EE, EE, nullptr);
    init_emb_k<<<8192, 1024>>>(mlp1, mlp2);
    scores_k<<<4 * BN / 8, 256>>>(cw1, cb1, cw2, cb2, lw1, lb1, lw2, lb2);

    // 5 iterations, one fused kernel each (launches 6-10)
    for (int it = 0; it < NITER; it++) {
        fused_k<<<dim3(4, 1, 128), 256, SMEMSZ>>>(
            cw1, cb1, cw2, cb2, lw1, lb1, lw2, lb2, (it == NITER - 1) ? 1 : 0);
    }

    // GRU chain (only consumed by outemb_k)
    sgemm<3><<<dim3(BB * TT / 128, 3, 1), 256>>>(SEM1, g1k, p_xz,                    BB * TT, 3 * EE, EE, g1b);
    sgemm<3><<<dim3(BB * TT / 128, 3, 1), 256>>>(SEM2, g2k, p_xz + BB * TT * 3 * EE, BB * TT, 3 * EE, EE, g2b);
    transpose_rk_k<<<2 * 3 * EE * EE / 256, 256>>>(g1rk, g2rk);
    gru_k<<<64, 384>>>(g1b, g2b);

    outemb_k<<<2 * BB, 64>>>(Wout, bout);
    final_k<<<BB, 64>>>((float*)d_out);
}